// round 8
// baseline (speedup 1.0000x reference)
#include <cuda_runtime.h>
#include <cuda_fp16.h>
#include <math.h>
#include <stdint.h>

#define B_ROWS 16384
#define D_DIM  1024
#define R_DIM  64
#define E_NUM  4
#define L_NUM  2
#define N1     256   // E * R

// ---------------------------------------------------------------------------
// Device scratch
// ---------------------------------------------------------------------------
__device__ __half g_W1h[L_NUM * N1 * D_DIM];   // [L][n=e*64+r][k=d]  fp16(V)
__device__ __half g_W2h[L_NUM * D_DIM * N1];   // [L][n=d][k=e*64+r]  fp16(U)
__device__ __half g_Xh [B_ROWS * D_DIM];       // fp16(x_l)
__device__ __half g_Zh [B_ROWS * N1];          // fp16(Z)
__device__ float g_H   [B_ROWS * N1];
__device__ float g_Xl  [B_ROWS * D_DIM];
__device__ float g_Gate[B_ROWS * E_NUM];

// ---------------------------------------------------------------------------
// Helpers
// ---------------------------------------------------------------------------
__device__ __forceinline__ uint32_t smem_u32(const void* p) {
    uint32_t a;
    asm("{ .reg .u64 t; cvta.to.shared.u64 t, %1; cvt.u32.u64 %0, t; }"
        : "=r"(a) : "l"(p));
    return a;
}

#define CP_ASYNC16(dst, src) \
    asm volatile("cp.async.cg.shared.global [%0], [%1], 16;" :: "r"(dst), "l"(src))
#define CP_COMMIT() asm volatile("cp.async.commit_group;" ::: "memory")
#define CP_WAIT3()  asm volatile("cp.async.wait_group 3;" ::: "memory")

#define LDSM_X4(r0, r1, r2, r3, addr) \
    asm volatile("ldmatrix.sync.aligned.m8n8.x4.shared.b16 {%0,%1,%2,%3}, [%4];" \
        : "=r"(r0), "=r"(r1), "=r"(r2), "=r"(r3) : "r"(addr))

#define MMA_F16(d, a, b0, b1) \
    asm volatile("mma.sync.aligned.m16n8k16.row.col.f32.f16.f16.f32 " \
        "{%0,%1,%2,%3}, {%4,%5,%6,%7}, {%8,%9}, {%0,%1,%2,%3};" \
        : "+f"((d)[0]), "+f"((d)[1]), "+f"((d)[2]), "+f"((d)[3]) \
        : "r"((a)[0]), "r"((a)[1]), "r"((a)[2]), "r"((a)[3]), "r"(b0), "r"(b1))

// ---------------------------------------------------------------------------
// Weight repack (fp16)
// ---------------------------------------------------------------------------
__global__ void repack_kernel(const float* __restrict__ U, const float* __restrict__ V) {
    int idx = blockIdx.x * blockDim.x + threadIdx.x;
    const int per = N1 * D_DIM;
    if (idx >= L_NUM * per) return;
    int i   = idx / per;
    int rem = idx - i * per;
    {   // W1[n][k] = V[i, e=n>>6, d=k, r=n&63]
        int n = rem / D_DIM, k = rem - (rem / D_DIM) * D_DIM;
        float v = V[(((size_t)i * E_NUM + (n >> 6)) * D_DIM + k) * R_DIM + (n & 63)];
        g_W1h[idx] = __float2half_rn(v);
    }
    {   // W2[d][k2] = U[i, e=k2>>6, d, r=k2&63]
        int d = rem / N1, k2 = rem - (rem / N1) * N1;
        float u = U[(((size_t)i * E_NUM + (k2 >> 6)) * D_DIM + d) * R_DIM + (k2 & 63)];
        g_W2h[(size_t)i * D_DIM * N1 + rem] = __float2half_rn(u);
    }
}

__global__ void convert_x_kernel(const float* __restrict__ x) {
    int i = (blockIdx.x * 256 + threadIdx.x) * 4;
    float4 v = *(const float4*)(x + i);
    __half2 h01, h23;
    h01.x = __float2half_rn(v.x); h01.y = __float2half_rn(v.y);
    h23.x = __float2half_rn(v.z); h23.y = __float2half_rn(v.w);
    *(__half2*)(g_Xh + i)     = h01;
    *(__half2*)(g_Xh + i + 2) = h23;
}

// ---------------------------------------------------------------------------
// Gate kernel: warp-per-row logits + softmax -> g_Gate[b][4]
// ---------------------------------------------------------------------------
__global__ void __launch_bounds__(256)
gate_kernel(const float* __restrict__ X, const float* __restrict__ gateW,
            float* __restrict__ gate)
{
    __shared__ float sG[E_NUM * D_DIM];
    const int tid = threadIdx.x;
    #pragma unroll
    for (int i = tid * 4; i < E_NUM * D_DIM; i += 1024)
        *(float4*)(sG + i) = *(const float4*)(gateW + i);
    __syncthreads();

    const int warp = tid >> 5, lane = tid & 31;
    const int b = blockIdx.x * 8 + warp;
    const float* xr = X + (size_t)b * D_DIM;

    float a0 = 0.f, a1 = 0.f, a2 = 0.f, a3 = 0.f;
    #pragma unroll
    for (int j = 0; j < 8; j++) {
        const int off = lane * 4 + j * 128;
        float4 xv = *(const float4*)(xr + off);
        float4 g0 = *(const float4*)(sG + 0 * D_DIM + off);
        float4 g1 = *(const float4*)(sG + 1 * D_DIM + off);
        float4 g2 = *(const float4*)(sG + 2 * D_DIM + off);
        float4 g3 = *(const float4*)(sG + 3 * D_DIM + off);
        a0 += xv.x * g0.x + xv.y * g0.y + xv.z * g0.z + xv.w * g0.w;
        a1 += xv.x * g1.x + xv.y * g1.y + xv.z * g1.z + xv.w * g1.w;
        a2 += xv.x * g2.x + xv.y * g2.y + xv.z * g2.z + xv.w * g2.w;
        a3 += xv.x * g3.x + xv.y * g3.y + xv.z * g3.z + xv.w * g3.w;
    }
    #pragma unroll
    for (int o = 16; o > 0; o >>= 1) {
        a0 += __shfl_xor_sync(0xffffffffu, a0, o);
        a1 += __shfl_xor_sync(0xffffffffu, a1, o);
        a2 += __shfl_xor_sync(0xffffffffu, a2, o);
        a3 += __shfl_xor_sync(0xffffffffu, a3, o);
    }
    float mx = fmaxf(fmaxf(a0, a1), fmaxf(a2, a3));
    float e0 = expf(a0 - mx), e1 = expf(a1 - mx), e2 = expf(a2 - mx), e3 = expf(a3 - mx);
    float inv = 1.0f / (e0 + e1 + e2 + e3);
    if (lane < 4) {
        float v = (lane == 0) ? e0 : (lane == 1) ? e1 : (lane == 2) ? e2 : e3;
        gate[b * 4 + lane] = v * inv;
    }
}

// ---------------------------------------------------------------------------
// Middle v2: register-resident C. Thread tid owns C row n=tid (64 regs).
// ---------------------------------------------------------------------------
__global__ void __launch_bounds__(256)
middle_kernel2(const float* __restrict__ C, const float* __restrict__ gate,
               const float* __restrict__ H, __half* __restrict__ Zh)
{
    __shared__ float sH[8][N1];
    const int tid = threadIdx.x;
    const int b0  = blockIdx.x * 8;
    const int e   = tid >> 6;

    float Creg[64];
    {
        const float* crow = C + (size_t)tid * 64;
        #pragma unroll
        for (int q = 0; q < 64; q += 4) {
            float4 v = *(const float4*)(crow + q);
            Creg[q + 0] = v.x; Creg[q + 1] = v.y;
            Creg[q + 2] = v.z; Creg[q + 3] = v.w;
        }
    }
    {
        const int row = tid >> 5;
        const int c   = (tid & 31) * 8;
        *(float4*)(&sH[row][c])     = *(const float4*)(H + (size_t)(b0 + row) * N1 + c);
        *(float4*)(&sH[row][c + 4]) = *(const float4*)(H + (size_t)(b0 + row) * N1 + c + 4);
    }
    __syncthreads();

    #pragma unroll
    for (int r = 0; r < 8; r++) {
        const float* hseg = &sH[r][e * 64];
        float acc = 0.0f;
        #pragma unroll
        for (int q = 0; q < 64; q++)
            acc = fmaf(Creg[q], hseg[q], acc);
        const float g = gate[(b0 + r) * 4 + e];
        Zh[(size_t)(b0 + r) * N1 + tid] = __float2half_rn(g * tanhf(acc));
    }
}

// ---------------------------------------------------------------------------
// Stage loader: 2 arrays (A, B), each 128 rows x 32 k (fp16) = 8KB.
// Panel layout: k-chunk kb (8 k) -> 128 rows x 16B at offset kb*2048 + row*16.
// ---------------------------------------------------------------------------
template<int KDIM>
__device__ __forceinline__ void load_stage(
    uint32_t sbase,
    const __half* __restrict__ A, const __half* __restrict__ B,
    int k0, int tid)
{
    #pragma unroll
    for (int h = 0; h < 2; h++) {
        int c   = tid + h * 256;       // 0..511
        int row = c >> 2;
        int kb  = c & 3;
        size_t   go = (size_t)row * KDIM + k0 + kb * 8;
        uint32_t so = (uint32_t)(kb * 2048 + row * 16);
        CP_ASYNC16(sbase +         so, A + go);
        CP_ASYNC16(sbase + 8192u + so, B + go);
    }
}

// ---------------------------------------------------------------------------
// fp16 mma GEMM: BM=128, BN=128, BK=32, 8 warps (4m x 2n).
// 5-stage cp.async pipeline, wait_group 3 (4 loads in flight).
// MODE 0: out = tanh(A@B)
// MODE 1: out = xl + x0*(A@B + bias)
// MODE 2: out = x0*(1 + A@B + bias), + fp16 copy of out
// ---------------------------------------------------------------------------
template<int MODE, int KDIM>
__global__ void __launch_bounds__(256, 2)
mma_gemm(const __half* __restrict__ Ag, const __half* __restrict__ Bg,
         const float* __restrict__ x0, const float* __restrict__ xl,
         const float* __restrict__ bias, float* __restrict__ out,
         __half* __restrict__ outh, int Nstride)
{
    constexpr int BK = 32, NK = KDIM / BK, NST = 5;
    constexpr uint32_t STAGE = 16384u;
    extern __shared__ char smem[];
    const uint32_t sbase = smem_u32(smem);

    const int tid  = threadIdx.x;
    const int wid  = tid >> 5;
    const int lane = tid & 31;
    const int wm   = wid & 3;
    const int wn   = wid >> 2;

    const __half* A = Ag + (size_t)blockIdx.y * 128 * KDIM;
    const __half* B = Bg + (size_t)blockIdx.x * 128 * KDIM;

    float acc[2][8][4];
    #pragma unroll
    for (int a = 0; a < 2; a++)
        #pragma unroll
        for (int b = 0; b < 8; b++)
            #pragma unroll
            for (int c = 0; c < 4; c++) acc[a][b][c] = 0.0f;

    // Prologue: fill 4 of 5 stages
    #pragma unroll
    for (int p = 0; p < 4; p++) {
        load_stage<KDIM>(sbase + (uint32_t)p * STAGE, A, B, p * BK, tid);
        CP_COMMIT();
    }

    const uint32_t arow16 = (uint32_t)((wm * 32 + (lane & 15)) * 16);
    const uint32_t asel   = (uint32_t)(lane >> 4) * 2048u;
    const uint32_t brow16 = (uint32_t)((wn * 64 + (lane & 7) + ((lane >> 4) << 3)) * 16);
    const uint32_t bsel   = (uint32_t)((lane >> 3) & 1) * 2048u;

    for (int i = 0; i < NK; i++) {
        CP_WAIT3();                   // stage i resident (<=3 groups pending)
        __syncthreads();
        if (i + 4 < NK) {
            load_stage<KDIM>(sbase + (uint32_t)((i + 4) % NST) * STAGE,
                             A, B, (i + 4) * BK, tid);
        }
        CP_COMMIT();

        const uint32_t st = sbase + (uint32_t)(i % NST) * STAGE;
        #pragma unroll
        for (int kk = 0; kk < 2; kk++) {
            const uint32_t kboff = (uint32_t)kk * 4096u;
            uint32_t ah[2][4], bb[4][4];

            #pragma unroll
            for (int g = 0; g < 4; g++) {
                uint32_t bd = st + 8192u + kboff + bsel + brow16 + (uint32_t)g * 256u;
                LDSM_X4(bb[g][0], bb[g][1], bb[g][2], bb[g][3], bd);
            }
            #pragma unroll
            for (int mt = 0; mt < 2; mt++) {
                uint32_t ad = st + kboff + asel + arow16 + (uint32_t)mt * 256u;
                LDSM_X4(ah[mt][0], ah[mt][1], ah[mt][2], ah[mt][3], ad);
            }
            #pragma unroll
            for (int mt = 0; mt < 2; mt++)
                #pragma unroll
                for (int nt = 0; nt < 8; nt++) {
                    const int g = nt >> 1, hh = (nt & 1) * 2;
                    MMA_F16(acc[mt][nt], ah[mt], bb[g][hh], bb[g][hh + 1]);
                }
        }
    }

    const int r0    = lane >> 2;
    const int cpair = (lane & 3) * 2;
    #pragma unroll
    for (int mt = 0; mt < 2; mt++)
        #pragma unroll
        for (int nt = 0; nt < 8; nt++) {
            const int row = blockIdx.y * 128 + wm * 32 + mt * 16 + r0;
            const int col = blockIdx.x * 128 + wn * 64 + nt * 8 + cpair;
            #pragma unroll
            for (int h = 0; h < 2; h++) {
                const int rr = row + h * 8;
                const float v0 = acc[mt][nt][h * 2 + 0];
                const float v1 = acc[mt][nt][h * 2 + 1];
                const size_t o = (size_t)rr * Nstride + col;
                if (MODE == 0) {
                    float2 ov;
                    ov.x = tanhf(v0);
                    ov.y = tanhf(v1);
                    *(float2*)(out + o) = ov;
                } else if (MODE == 1) {
                    const float2 bv = *(const float2*)(bias + col);
                    const float2 xv = *(const float2*)(x0 + o);
                    const float2 lv = *(const float2*)(xl + o);
                    float2 ov;
                    ov.x = fmaf(xv.x, v0 + bv.x, lv.x);
                    ov.y = fmaf(xv.y, v1 + bv.y, lv.y);
                    *(float2*)(out + o) = ov;
                } else {
                    const float2 bv = *(const float2*)(bias + col);
                    const float2 xv = *(const float2*)(x0 + o);
                    float2 ov;
                    ov.x = xv.x * (1.0f + v0 + bv.x);
                    ov.y = xv.y * (1.0f + v1 + bv.y);
                    *(float2*)(out + o) = ov;
                    __half2 hv;
                    hv.x = __float2half_rn(ov.x);
                    hv.y = __float2half_rn(ov.y);
                    *(__half2*)(outh + o) = hv;
                }
            }
        }
}

// ---------------------------------------------------------------------------
extern "C" void kernel_launch(void* const* d_in, const int* in_sizes, int n_in,
                              void* d_out, int out_size)
{
    const float* x     = (const float*)d_in[0];
    const float* U     = (const float*)d_in[1];
    const float* V     = (const float*)d_in[2];
    const float* C     = (const float*)d_in[3];
    const float* bias  = (const float*)d_in[4];
    const float* gateW = (const float*)d_in[5];
    float* out = (float*)d_out;

    __half *w1h, *w2h, *xh, *zh;
    float *hbuf, *xlbuf, *gbuf;
    cudaGetSymbolAddress((void**)&w1h,   g_W1h);
    cudaGetSymbolAddress((void**)&w2h,   g_W2h);
    cudaGetSymbolAddress((void**)&xh,    g_Xh);
    cudaGetSymbolAddress((void**)&zh,    g_Zh);
    cudaGetSymbolAddress((void**)&hbuf,  g_H);
    cudaGetSymbolAddress((void**)&xlbuf, g_Xl);
    cudaGetSymbolAddress((void**)&gbuf,  g_Gate);

    const int GEMM_SMEM = 5 * 16384;
    cudaFuncSetAttribute(mma_gemm<0, 1024>, cudaFuncAttributeMaxDynamicSharedMemorySize, GEMM_SMEM);
    cudaFuncSetAttribute(mma_gemm<1, 256>,  cudaFuncAttributeMaxDynamicSharedMemorySize, GEMM_SMEM);
    cudaFuncSetAttribute(mma_gemm<2, 256>,  cudaFuncAttributeMaxDynamicSharedMemorySize, GEMM_SMEM);

    repack_kernel<<<(L_NUM * N1 * D_DIM + 255) / 256, 256>>>(U, V);
    convert_x_kernel<<<B_ROWS * D_DIM / 4 / 256, 256>>>(x);

    for (int i = 0; i < L_NUM; i++) {
        const float* xin = (i == 0) ? x : xlbuf;
        const size_t woff = (size_t)i * N1 * D_DIM;
        const float* Cl = C + (size_t)i * E_NUM * R_DIM * R_DIM;

        // GEMM1: H = tanh(X @ W1^T)   [16384 x 256], K = 1024
        mma_gemm<0, 1024><<<dim3(2, B_ROWS / 128), 256, GEMM_SMEM>>>(
            xh, w1h + woff, nullptr, nullptr, nullptr, hbuf, nullptr, N1);

        gate_kernel<<<B_ROWS / 8, 256>>>(xin, gateW, gbuf);

        middle_kernel2<<<B_ROWS / 8, 256>>>(Cl, gbuf, hbuf, zh);

        // GEMM2: out = xl + x0*(Z @ W2^T + bias)  [16384 x 1024], K = 256
        if (i == 0) {
            mma_gemm<2, 256><<<dim3(8, B_ROWS / 128), 256, GEMM_SMEM>>>(
                zh, w2h + woff, x, nullptr, bias, xlbuf, xh, D_DIM);
        } else {
            mma_gemm<1, 256><<<dim3(8, B_ROWS / 128), 256, GEMM_SMEM>>>(
                zh, w2h + woff, x, xin, bias + (size_t)i * D_DIM, out, nullptr, D_DIM);
        }
    }
}

// round 9
// speedup vs baseline: 1.0165x; 1.0165x over previous
#include <cuda_runtime.h>
#include <cuda_fp16.h>
#include <math.h>
#include <stdint.h>

#define B_ROWS 16384
#define D_DIM  1024
#define R_DIM  64
#define E_NUM  4
#define L_NUM  2
#define N1     256   // E * R

// ---------------------------------------------------------------------------
// Device scratch (all intermediates fp16)
// ---------------------------------------------------------------------------
__device__ __half g_W1h[L_NUM * N1 * D_DIM];   // [L][n=e*64+r][k=d]  fp16(V)
__device__ __half g_W2h[L_NUM * D_DIM * N1];   // [L][n=d][k=e*64+r]  fp16(U)
__device__ __half g_Xh [B_ROWS * D_DIM];       // fp16(x_l)  (current layer input)
__device__ __half g_X0h[B_ROWS * D_DIM];       // fp16(x0)
__device__ __half g_Zh [B_ROWS * N1];          // fp16(Z)
__device__ __half g_Hh [B_ROWS * N1];          // fp16(H)
__device__ float g_Gate[B_ROWS * E_NUM];

// ---------------------------------------------------------------------------
// Helpers
// ---------------------------------------------------------------------------
__device__ __forceinline__ uint32_t smem_u32(const void* p) {
    uint32_t a;
    asm("{ .reg .u64 t; cvta.to.shared.u64 t, %1; cvt.u32.u64 %0, t; }"
        : "=r"(a) : "l"(p));
    return a;
}

#define CP_ASYNC16(dst, src) \
    asm volatile("cp.async.cg.shared.global [%0], [%1], 16;" :: "r"(dst), "l"(src))
#define CP_COMMIT() asm volatile("cp.async.commit_group;" ::: "memory")
#define CP_WAIT3()  asm volatile("cp.async.wait_group 3;" ::: "memory")

#define LDSM_X4(r0, r1, r2, r3, addr) \
    asm volatile("ldmatrix.sync.aligned.m8n8.x4.shared.b16 {%0,%1,%2,%3}, [%4];" \
        : "=r"(r0), "=r"(r1), "=r"(r2), "=r"(r3) : "r"(addr))

#define MMA_F16(d, a, b0, b1) \
    asm volatile("mma.sync.aligned.m16n8k16.row.col.f32.f16.f16.f32 " \
        "{%0,%1,%2,%3}, {%4,%5,%6,%7}, {%8,%9}, {%0,%1,%2,%3};" \
        : "+f"((d)[0]), "+f"((d)[1]), "+f"((d)[2]), "+f"((d)[3]) \
        : "r"((a)[0]), "r"((a)[1]), "r"((a)[2]), "r"((a)[3]), "r"(b0), "r"(b1))

// ---------------------------------------------------------------------------
// Weight repack (fp16)
// ---------------------------------------------------------------------------
__global__ void repack_kernel(const float* __restrict__ U, const float* __restrict__ V) {
    int idx = blockIdx.x * blockDim.x + threadIdx.x;
    const int per = N1 * D_DIM;
    if (idx >= L_NUM * per) return;
    int i   = idx / per;
    int rem = idx - i * per;
    {   // W1[n][k] = V[i, e=n>>6, d=k, r=n&63]
        int n = rem / D_DIM, k = rem - (rem / D_DIM) * D_DIM;
        float v = V[(((size_t)i * E_NUM + (n >> 6)) * D_DIM + k) * R_DIM + (n & 63)];
        g_W1h[idx] = __float2half_rn(v);
    }
    {   // W2[d][k2] = U[i, e=k2>>6, d, r=k2&63]
        int d = rem / N1, k2 = rem - (rem / N1) * N1;
        float u = U[(((size_t)i * E_NUM + (k2 >> 6)) * D_DIM + d) * R_DIM + (k2 & 63)];
        g_W2h[(size_t)i * D_DIM * N1 + rem] = __float2half_rn(u);
    }
}

__global__ void convert_x_kernel(const float* __restrict__ x) {
    int i = (blockIdx.x * 256 + threadIdx.x) * 4;
    float4 v = *(const float4*)(x + i);
    __half2 h01, h23;
    h01.x = __float2half_rn(v.x); h01.y = __float2half_rn(v.y);
    h23.x = __float2half_rn(v.z); h23.y = __float2half_rn(v.w);
    *(__half2*)(g_Xh + i)      = h01;
    *(__half2*)(g_Xh + i + 2)  = h23;
    *(__half2*)(g_X0h + i)     = h01;
    *(__half2*)(g_X0h + i + 2) = h23;
}

// ---------------------------------------------------------------------------
// Gate kernel (fp16 X): warp-per-row logits + softmax -> g_Gate[b][4]
// ---------------------------------------------------------------------------
__global__ void __launch_bounds__(256)
gate_kernel(const __half* __restrict__ Xh, const float* __restrict__ gateW,
            float* __restrict__ gate)
{
    __shared__ float sG[E_NUM * D_DIM];
    const int tid = threadIdx.x;
    #pragma unroll
    for (int i = tid * 4; i < E_NUM * D_DIM; i += 1024)
        *(float4*)(sG + i) = *(const float4*)(gateW + i);
    __syncthreads();

    const int warp = tid >> 5, lane = tid & 31;
    const int b = blockIdx.x * 8 + warp;
    const __half* xr = Xh + (size_t)b * D_DIM;

    float a0 = 0.f, a1 = 0.f, a2 = 0.f, a3 = 0.f;
    #pragma unroll
    for (int j = 0; j < 4; j++) {
        const int off = lane * 8 + j * 256;
        uint4 xv4 = *(const uint4*)(xr + off);
        float2 xf[4];
        xf[0] = __half22float2(*(__half2*)&xv4.x);
        xf[1] = __half22float2(*(__half2*)&xv4.y);
        xf[2] = __half22float2(*(__half2*)&xv4.z);
        xf[3] = __half22float2(*(__half2*)&xv4.w);
        #pragma unroll
        for (int e = 0; e < E_NUM; e++) {
            float4 ga = *(const float4*)(sG + e * D_DIM + off);
            float4 gb = *(const float4*)(sG + e * D_DIM + off + 4);
            float p = xf[0].x * ga.x + xf[0].y * ga.y
                    + xf[1].x * ga.z + xf[1].y * ga.w
                    + xf[2].x * gb.x + xf[2].y * gb.y
                    + xf[3].x * gb.z + xf[3].y * gb.w;
            if (e == 0) a0 += p; else if (e == 1) a1 += p;
            else if (e == 2) a2 += p; else a3 += p;
        }
    }
    #pragma unroll
    for (int o = 16; o > 0; o >>= 1) {
        a0 += __shfl_xor_sync(0xffffffffu, a0, o);
        a1 += __shfl_xor_sync(0xffffffffu, a1, o);
        a2 += __shfl_xor_sync(0xffffffffu, a2, o);
        a3 += __shfl_xor_sync(0xffffffffu, a3, o);
    }
    float mx = fmaxf(fmaxf(a0, a1), fmaxf(a2, a3));
    float e0 = expf(a0 - mx), e1 = expf(a1 - mx), e2 = expf(a2 - mx), e3 = expf(a3 - mx);
    float inv = 1.0f / (e0 + e1 + e2 + e3);
    if (lane < 4) {
        float v = (lane == 0) ? e0 : (lane == 1) ? e1 : (lane == 2) ? e2 : e3;
        gate[b * 4 + lane] = v * inv;
    }
}

// ---------------------------------------------------------------------------
// Middle: register-resident C; H read as fp16, staged to fp32 smem.
// ---------------------------------------------------------------------------
__global__ void __launch_bounds__(256)
middle_kernel2(const float* __restrict__ C, const float* __restrict__ gate,
               const __half* __restrict__ Hh, __half* __restrict__ Zh)
{
    __shared__ float sH[8][N1];
    const int tid = threadIdx.x;
    const int b0  = blockIdx.x * 8;
    const int e   = tid >> 6;

    float Creg[64];
    {
        const float* crow = C + (size_t)tid * 64;
        #pragma unroll
        for (int q = 0; q < 64; q += 4) {
            float4 v = *(const float4*)(crow + q);
            Creg[q + 0] = v.x; Creg[q + 1] = v.y;
            Creg[q + 2] = v.z; Creg[q + 3] = v.w;
        }
    }
    {
        const int row = tid >> 5;
        const int c   = (tid & 31) * 8;
        uint4 hv = *(const uint4*)(Hh + (size_t)(b0 + row) * N1 + c);
        float2 f0 = __half22float2(*(__half2*)&hv.x);
        float2 f1 = __half22float2(*(__half2*)&hv.y);
        float2 f2 = __half22float2(*(__half2*)&hv.z);
        float2 f3 = __half22float2(*(__half2*)&hv.w);
        sH[row][c + 0] = f0.x; sH[row][c + 1] = f0.y;
        sH[row][c + 2] = f1.x; sH[row][c + 3] = f1.y;
        sH[row][c + 4] = f2.x; sH[row][c + 5] = f2.y;
        sH[row][c + 6] = f3.x; sH[row][c + 7] = f3.y;
    }
    __syncthreads();

    #pragma unroll
    for (int r = 0; r < 8; r++) {
        const float* hseg = &sH[r][e * 64];
        float acc = 0.0f;
        #pragma unroll
        for (int q = 0; q < 64; q++)
            acc = fmaf(Creg[q], hseg[q], acc);
        const float g = gate[(b0 + r) * 4 + e];
        Zh[(size_t)(b0 + r) * N1 + tid] = __float2half_rn(g * tanhf(acc));
    }
}

// ---------------------------------------------------------------------------
// Stage loader: 2 arrays (A, B), each 128 rows x 32 k (fp16) = 8KB.
// ---------------------------------------------------------------------------
template<int KDIM>
__device__ __forceinline__ void load_stage(
    uint32_t sbase,
    const __half* __restrict__ A, const __half* __restrict__ B,
    int k0, int tid)
{
    #pragma unroll
    for (int h = 0; h < 2; h++) {
        int c   = tid + h * 256;       // 0..511
        int row = c >> 2;
        int kb  = c & 3;
        size_t   go = (size_t)row * KDIM + k0 + kb * 8;
        uint32_t so = (uint32_t)(kb * 2048 + row * 16);
        CP_ASYNC16(sbase +         so, A + go);
        CP_ASYNC16(sbase + 8192u + so, B + go);
    }
}

// ---------------------------------------------------------------------------
// fp16 mma GEMM: BM=128, BN=128, BK=32, 8 warps (4m x 2n), 5-stage pipeline.
// MODE 0: outh = fp16(tanh(A@B))
// MODE 1: out  = xlh + x0h*(A@B + bias)          (fp32 final output)
// MODE 2: outh = fp16(x0h*(1 + A@B + bias))      (layer-0; xl==x0)
// ---------------------------------------------------------------------------
template<int MODE, int KDIM>
__global__ void __launch_bounds__(256, 2)
mma_gemm(const __half* __restrict__ Ag, const __half* __restrict__ Bg,
         const __half* __restrict__ x0h, const __half* __restrict__ xlh,
         const float* __restrict__ bias, float* __restrict__ out,
         __half* __restrict__ outh, int Nstride)
{
    constexpr int BK = 32, NK = KDIM / BK, NST = 5;
    constexpr uint32_t STAGE = 16384u;
    extern __shared__ char smem[];
    const uint32_t sbase = smem_u32(smem);

    const int tid  = threadIdx.x;
    const int wid  = tid >> 5;
    const int lane = tid & 31;
    const int wm   = wid & 3;
    const int wn   = wid >> 2;

    const __half* A = Ag + (size_t)blockIdx.y * 128 * KDIM;
    const __half* B = Bg + (size_t)blockIdx.x * 128 * KDIM;

    float acc[2][8][4];
    #pragma unroll
    for (int a = 0; a < 2; a++)
        #pragma unroll
        for (int b = 0; b < 8; b++)
            #pragma unroll
            for (int c = 0; c < 4; c++) acc[a][b][c] = 0.0f;

    #pragma unroll
    for (int p = 0; p < 4; p++) {
        load_stage<KDIM>(sbase + (uint32_t)p * STAGE, A, B, p * BK, tid);
        CP_COMMIT();
    }

    const uint32_t arow16 = (uint32_t)((wm * 32 + (lane & 15)) * 16);
    const uint32_t asel   = (uint32_t)(lane >> 4) * 2048u;
    const uint32_t brow16 = (uint32_t)((wn * 64 + (lane & 7) + ((lane >> 4) << 3)) * 16);
    const uint32_t bsel   = (uint32_t)((lane >> 3) & 1) * 2048u;

    for (int i = 0; i < NK; i++) {
        CP_WAIT3();
        __syncthreads();
        if (i + 4 < NK) {
            load_stage<KDIM>(sbase + (uint32_t)((i + 4) % NST) * STAGE,
                             A, B, (i + 4) * BK, tid);
        }
        CP_COMMIT();

        const uint32_t st = sbase + (uint32_t)(i % NST) * STAGE;
        #pragma unroll
        for (int kk = 0; kk < 2; kk++) {
            const uint32_t kboff = (uint32_t)kk * 4096u;
            uint32_t ah[2][4], bb[4][4];

            #pragma unroll
            for (int g = 0; g < 4; g++) {
                uint32_t bd = st + 8192u + kboff + bsel + brow16 + (uint32_t)g * 256u;
                LDSM_X4(bb[g][0], bb[g][1], bb[g][2], bb[g][3], bd);
            }
            #pragma unroll
            for (int mt = 0; mt < 2; mt++) {
                uint32_t ad = st + kboff + asel + arow16 + (uint32_t)mt * 256u;
                LDSM_X4(ah[mt][0], ah[mt][1], ah[mt][2], ah[mt][3], ad);
            }
            #pragma unroll
            for (int mt = 0; mt < 2; mt++)
                #pragma unroll
                for (int nt = 0; nt < 8; nt++) {
                    const int g = nt >> 1, hh = (nt & 1) * 2;
                    MMA_F16(acc[mt][nt], ah[mt], bb[g][hh], bb[g][hh + 1]);
                }
        }
    }

    const int r0    = lane >> 2;
    const int cpair = (lane & 3) * 2;
    #pragma unroll
    for (int mt = 0; mt < 2; mt++)
        #pragma unroll
        for (int nt = 0; nt < 8; nt++) {
            const int row = blockIdx.y * 128 + wm * 32 + mt * 16 + r0;
            const int col = blockIdx.x * 128 + wn * 64 + nt * 8 + cpair;
            #pragma unroll
            for (int h = 0; h < 2; h++) {
                const int rr = row + h * 8;
                const float v0 = acc[mt][nt][h * 2 + 0];
                const float v1 = acc[mt][nt][h * 2 + 1];
                const size_t o = (size_t)rr * Nstride + col;
                if (MODE == 0) {
                    __half2 hv;
                    hv.x = __float2half_rn(tanhf(v0));
                    hv.y = __float2half_rn(tanhf(v1));
                    *(__half2*)(outh + o) = hv;
                } else if (MODE == 1) {
                    const float2 bv = *(const float2*)(bias + col);
                    const float2 xf = __half22float2(*(const __half2*)(x0h + o));
                    const float2 lf = __half22float2(*(const __half2*)(xlh + o));
                    float2 ov;
                    ov.x = fmaf(xf.x, v0 + bv.x, lf.x);
                    ov.y = fmaf(xf.y, v1 + bv.y, lf.y);
                    *(float2*)(out + o) = ov;
                } else {
                    const float2 bv = *(const float2*)(bias + col);
                    const float2 xf = __half22float2(*(const __half2*)(x0h + o));
                    __half2 hv;
                    hv.x = __float2half_rn(xf.x * (1.0f + v0 + bv.x));
                    hv.y = __float2half_rn(xf.y * (1.0f + v1 + bv.y));
                    *(__half2*)(outh + o) = hv;
                }
            }
        }
}

// ---------------------------------------------------------------------------
extern "C" void kernel_launch(void* const* d_in, const int* in_sizes, int n_in,
                              void* d_out, int out_size)
{
    const float* x     = (const float*)d_in[0];
    const float* U     = (const float*)d_in[1];
    const float* V     = (const float*)d_in[2];
    const float* C     = (const float*)d_in[3];
    const float* bias  = (const float*)d_in[4];
    const float* gateW = (const float*)d_in[5];
    float* out = (float*)d_out;

    __half *w1h, *w2h, *xh, *x0h, *zh, *hh;
    float *gbuf;
    cudaGetSymbolAddress((void**)&w1h,  g_W1h);
    cudaGetSymbolAddress((void**)&w2h,  g_W2h);
    cudaGetSymbolAddress((void**)&xh,   g_Xh);
    cudaGetSymbolAddress((void**)&x0h,  g_X0h);
    cudaGetSymbolAddress((void**)&zh,   g_Zh);
    cudaGetSymbolAddress((void**)&hh,   g_Hh);
    cudaGetSymbolAddress((void**)&gbuf, g_Gate);

    const int GEMM_SMEM = 5 * 16384;
    cudaFuncSetAttribute(mma_gemm<0, 1024>, cudaFuncAttributeMaxDynamicSharedMemorySize, GEMM_SMEM);
    cudaFuncSetAttribute(mma_gemm<1, 256>,  cudaFuncAttributeMaxDynamicSharedMemorySize, GEMM_SMEM);
    cudaFuncSetAttribute(mma_gemm<2, 256>,  cudaFuncAttributeMaxDynamicSharedMemorySize, GEMM_SMEM);

    repack_kernel<<<(L_NUM * N1 * D_DIM + 255) / 256, 256>>>(U, V);
    convert_x_kernel<<<B_ROWS * D_DIM / 4 / 256, 256>>>(x);

    for (int i = 0; i < L_NUM; i++) {
        const size_t woff = (size_t)i * N1 * D_DIM;
        const float* Cl = C + (size_t)i * E_NUM * R_DIM * R_DIM;

        // GEMM1: Hh = fp16(tanh(Xh @ W1^T))   [16384 x 256], K = 1024
        mma_gemm<0, 1024><<<dim3(2, B_ROWS / 128), 256, GEMM_SMEM>>>(
            xh, w1h + woff, nullptr, nullptr, nullptr, nullptr, hh, N1);

        gate_kernel<<<B_ROWS / 8, 256>>>(xh, gateW, gbuf);

        middle_kernel2<<<B_ROWS / 8, 256>>>(Cl, gbuf, hh, zh);

        // GEMM2  [16384 x 1024], K = 256
        if (i == 0) {
            // xh <- fp16(x0*(1 + Z@W2^T + bias))
            mma_gemm<2, 256><<<dim3(8, B_ROWS / 128), 256, GEMM_SMEM>>>(
                zh, w2h + woff, x0h, nullptr, bias, nullptr, xh, D_DIM);
        } else {
            // out = xh + x0*(Z@W2^T + bias)
            mma_gemm<1, 256><<<dim3(8, B_ROWS / 128), 256, GEMM_SMEM>>>(
                zh, w2h + woff, x0h, xh, bias + (size_t)i * D_DIM, out, nullptr, D_DIM);
        }
    }
}

// round 10
// speedup vs baseline: 1.0569x; 1.0398x over previous
#include <cuda_runtime.h>
#include <cuda_fp16.h>
#include <math.h>
#include <stdint.h>

#define B_ROWS 16384
#define D_DIM  1024
#define R_DIM  64
#define E_NUM  4
#define L_NUM  2
#define N1     256   // E * R

// ---------------------------------------------------------------------------
// Device scratch (all intermediates fp16)
// ---------------------------------------------------------------------------
__device__ __half g_W1h[L_NUM * N1 * D_DIM];   // [L][n=e*64+r][k=d]  fp16(V)
__device__ __half g_W2h[L_NUM * D_DIM * N1];   // [L][n=d][k=e*64+r]  fp16(U)
__device__ __half g_Xh [B_ROWS * D_DIM];       // fp16(x_l) after layer 0
__device__ __half g_X0h[B_ROWS * D_DIM];       // fp16(x0)
__device__ __half g_Zh [B_ROWS * N1];          // fp16(Z)
__device__ __half g_Hh [B_ROWS * N1];          // fp16(H)

// ---------------------------------------------------------------------------
// Helpers
// ---------------------------------------------------------------------------
__device__ __forceinline__ uint32_t smem_u32(const void* p) {
    uint32_t a;
    asm("{ .reg .u64 t; cvta.to.shared.u64 t, %1; cvt.u32.u64 %0, t; }"
        : "=r"(a) : "l"(p));
    return a;
}

#define CP_ASYNC16(dst, src) \
    asm volatile("cp.async.cg.shared.global [%0], [%1], 16;" :: "r"(dst), "l"(src))
#define CP_COMMIT() asm volatile("cp.async.commit_group;" ::: "memory")
#define CP_WAIT3()  asm volatile("cp.async.wait_group 3;" ::: "memory")

#define LDSM_X4(r0, r1, r2, r3, addr) \
    asm volatile("ldmatrix.sync.aligned.m8n8.x4.shared.b16 {%0,%1,%2,%3}, [%4];" \
        : "=r"(r0), "=r"(r1), "=r"(r2), "=r"(r3) : "r"(addr))

#define MMA_F16(d, a, b0, b1) \
    asm volatile("mma.sync.aligned.m16n8k16.row.col.f32.f16.f16.f32 " \
        "{%0,%1,%2,%3}, {%4,%5,%6,%7}, {%8,%9}, {%0,%1,%2,%3};" \
        : "+f"((d)[0]), "+f"((d)[1]), "+f"((d)[2]), "+f"((d)[3]) \
        : "r"((a)[0]), "r"((a)[1]), "r"((a)[2]), "r"((a)[3]), "r"(b0), "r"(b1))

// ---------------------------------------------------------------------------
// Weight repack (fp16)
// ---------------------------------------------------------------------------
__global__ void repack_kernel(const float* __restrict__ U, const float* __restrict__ V) {
    int idx = blockIdx.x * blockDim.x + threadIdx.x;
    const int per = N1 * D_DIM;
    if (idx >= L_NUM * per) return;
    int i   = idx / per;
    int rem = idx - i * per;
    {   // W1[n][k] = V[i, e=n>>6, d=k, r=n&63]
        int n = rem / D_DIM, k = rem - (rem / D_DIM) * D_DIM;
        float v = V[(((size_t)i * E_NUM + (n >> 6)) * D_DIM + k) * R_DIM + (n & 63)];
        g_W1h[idx] = __float2half_rn(v);
    }
    {   // W2[d][k2] = U[i, e=k2>>6, d, r=k2&63]
        int d = rem / N1, k2 = rem - (rem / N1) * N1;
        float u = U[(((size_t)i * E_NUM + (k2 >> 6)) * D_DIM + d) * R_DIM + (k2 & 63)];
        g_W2h[(size_t)i * D_DIM * N1 + rem] = __float2half_rn(u);
    }
}

__global__ void convert_x_kernel(const float* __restrict__ x) {
    int i = (blockIdx.x * 256 + threadIdx.x) * 4;
    float4 v = *(const float4*)(x + i);
    __half2 h01, h23;
    h01.x = __float2half_rn(v.x); h01.y = __float2half_rn(v.y);
    h23.x = __float2half_rn(v.z); h23.y = __float2half_rn(v.w);
    *(__half2*)(g_X0h + i)     = h01;
    *(__half2*)(g_X0h + i + 2) = h23;
}

// ---------------------------------------------------------------------------
// Fused gate + middle: one block per 8 batch rows.
//  - warp w computes gate logits for row b0+w (X dot gateW, fp32 gateW in smem)
//  - softmax per row -> sGate
//  - register-resident C (thread tid owns C row n=tid), Z = gate * tanh(C.H)
// ---------------------------------------------------------------------------
__global__ void __launch_bounds__(256)
fused_mid(const __half* __restrict__ Xh, const float* __restrict__ gateW,
          const float* __restrict__ C, const __half* __restrict__ Hh,
          __half* __restrict__ Zh)
{
    __shared__ float sG[E_NUM * D_DIM];   // 16 KB
    __shared__ float sH[8][N1];           // 8 KB
    __shared__ float sGate[8][E_NUM];

    const int tid  = threadIdx.x;
    const int warp = tid >> 5, lane = tid & 31;
    const int b0   = blockIdx.x * 8;
    const int e    = tid >> 6;

    // stage gateW (fp32) into smem
    #pragma unroll
    for (int i = tid * 4; i < E_NUM * D_DIM; i += 1024)
        *(float4*)(sG + i) = *(const float4*)(gateW + i);

    // stage H rows (fp16 -> fp32 smem)
    {
        const int row = tid >> 5;
        const int c   = (tid & 31) * 8;
        uint4 hv = *(const uint4*)(Hh + (size_t)(b0 + row) * N1 + c);
        float2 f0 = __half22float2(*(__half2*)&hv.x);
        float2 f1 = __half22float2(*(__half2*)&hv.y);
        float2 f2 = __half22float2(*(__half2*)&hv.z);
        float2 f3 = __half22float2(*(__half2*)&hv.w);
        sH[row][c + 0] = f0.x; sH[row][c + 1] = f0.y;
        sH[row][c + 2] = f1.x; sH[row][c + 3] = f1.y;
        sH[row][c + 4] = f2.x; sH[row][c + 5] = f2.y;
        sH[row][c + 6] = f3.x; sH[row][c + 7] = f3.y;
    }
    __syncthreads();

    // gate logits: warp w owns row b0+w
    {
        const __half* xr = Xh + (size_t)(b0 + warp) * D_DIM;
        float a0 = 0.f, a1 = 0.f, a2 = 0.f, a3 = 0.f;
        #pragma unroll
        for (int j = 0; j < 4; j++) {
            const int off = lane * 8 + j * 256;
            uint4 xv4 = *(const uint4*)(xr + off);
            float2 xf[4];
            xf[0] = __half22float2(*(__half2*)&xv4.x);
            xf[1] = __half22float2(*(__half2*)&xv4.y);
            xf[2] = __half22float2(*(__half2*)&xv4.z);
            xf[3] = __half22float2(*(__half2*)&xv4.w);
            #pragma unroll
            for (int ee = 0; ee < E_NUM; ee++) {
                float4 ga = *(const float4*)(sG + ee * D_DIM + off);
                float4 gb = *(const float4*)(sG + ee * D_DIM + off + 4);
                float p = xf[0].x * ga.x + xf[0].y * ga.y
                        + xf[1].x * ga.z + xf[1].y * ga.w
                        + xf[2].x * gb.x + xf[2].y * gb.y
                        + xf[3].x * gb.z + xf[3].y * gb.w;
                if (ee == 0) a0 += p; else if (ee == 1) a1 += p;
                else if (ee == 2) a2 += p; else a3 += p;
            }
        }
        #pragma unroll
        for (int o = 16; o > 0; o >>= 1) {
            a0 += __shfl_xor_sync(0xffffffffu, a0, o);
            a1 += __shfl_xor_sync(0xffffffffu, a1, o);
            a2 += __shfl_xor_sync(0xffffffffu, a2, o);
            a3 += __shfl_xor_sync(0xffffffffu, a3, o);
        }
        float mx = fmaxf(fmaxf(a0, a1), fmaxf(a2, a3));
        float e0 = expf(a0 - mx), e1 = expf(a1 - mx);
        float e2 = expf(a2 - mx), e3 = expf(a3 - mx);
        float inv = 1.0f / (e0 + e1 + e2 + e3);
        if (lane < 4) {
            float v = (lane == 0) ? e0 : (lane == 1) ? e1 : (lane == 2) ? e2 : e3;
            sGate[warp][lane] = v * inv;
        }
    }

    // register-resident C row n=tid
    float Creg[64];
    {
        const float* crow = C + (size_t)tid * 64;
        #pragma unroll
        for (int q = 0; q < 64; q += 4) {
            float4 v = *(const float4*)(crow + q);
            Creg[q + 0] = v.x; Creg[q + 1] = v.y;
            Creg[q + 2] = v.z; Creg[q + 3] = v.w;
        }
    }
    __syncthreads();

    #pragma unroll
    for (int r = 0; r < 8; r++) {
        const float* hseg = &sH[r][e * 64];
        float acc = 0.0f;
        #pragma unroll
        for (int q = 0; q < 64; q++)
            acc = fmaf(Creg[q], hseg[q], acc);
        const float g = sGate[r][e];
        Zh[(size_t)(b0 + r) * N1 + tid] = __float2half_rn(g * tanhf(acc));
    }
}

// ---------------------------------------------------------------------------
// Stage loader: 2 arrays (A, B), each 128 rows x 32 k (fp16) = 8KB.
// ---------------------------------------------------------------------------
template<int KDIM>
__device__ __forceinline__ void load_stage(
    uint32_t sbase,
    const __half* __restrict__ A, const __half* __restrict__ B,
    int k0, int tid)
{
    #pragma unroll
    for (int h = 0; h < 2; h++) {
        int c   = tid + h * 256;       // 0..511
        int row = c >> 2;
        int kb  = c & 3;
        size_t   go = (size_t)row * KDIM + k0 + kb * 8;
        uint32_t so = (uint32_t)(kb * 2048 + row * 16);
        CP_ASYNC16(sbase +         so, A + go);
        CP_ASYNC16(sbase + 8192u + so, B + go);
    }
}

// ---------------------------------------------------------------------------
// fp16 mma GEMM: BM=128, BN=128, BK=32, 8 warps (4m x 2n), 5-stage pipeline.
// MODE 0: outh = fp16(tanh(A@B))
// MODE 1: out  = xlh + x0h*(A@B + bias)          (fp32 final output)
// MODE 2: outh = fp16(x0h*(1 + A@B + bias))      (layer-0; xl==x0)
// ---------------------------------------------------------------------------
template<int MODE, int KDIM>
__global__ void __launch_bounds__(256, 2)
mma_gemm(const __half* __restrict__ Ag, const __half* __restrict__ Bg,
         const __half* __restrict__ x0h, const __half* __restrict__ xlh,
         const float* __restrict__ bias, float* __restrict__ out,
         __half* __restrict__ outh, int Nstride)
{
    constexpr int BK = 32, NK = KDIM / BK, NST = 5;
    constexpr uint32_t STAGE = 16384u;
    extern __shared__ char smem[];
    const uint32_t sbase = smem_u32(smem);

    const int tid  = threadIdx.x;
    const int wid  = tid >> 5;
    const int lane = tid & 31;
    const int wm   = wid & 3;
    const int wn   = wid >> 2;

    const __half* A = Ag + (size_t)blockIdx.y * 128 * KDIM;
    const __half* B = Bg + (size_t)blockIdx.x * 128 * KDIM;

    float acc[2][8][4];
    #pragma unroll
    for (int a = 0; a < 2; a++)
        #pragma unroll
        for (int b = 0; b < 8; b++)
            #pragma unroll
            for (int c = 0; c < 4; c++) acc[a][b][c] = 0.0f;

    #pragma unroll
    for (int p = 0; p < 4; p++) {
        load_stage<KDIM>(sbase + (uint32_t)p * STAGE, A, B, p * BK, tid);
        CP_COMMIT();
    }

    const uint32_t arow16 = (uint32_t)((wm * 32 + (lane & 15)) * 16);
    const uint32_t asel   = (uint32_t)(lane >> 4) * 2048u;
    const uint32_t brow16 = (uint32_t)((wn * 64 + (lane & 7) + ((lane >> 4) << 3)) * 16);
    const uint32_t bsel   = (uint32_t)((lane >> 3) & 1) * 2048u;

    for (int i = 0; i < NK; i++) {
        CP_WAIT3();
        __syncthreads();
        if (i + 4 < NK) {
            load_stage<KDIM>(sbase + (uint32_t)((i + 4) % NST) * STAGE,
                             A, B, (i + 4) * BK, tid);
        }
        CP_COMMIT();

        const uint32_t st = sbase + (uint32_t)(i % NST) * STAGE;
        #pragma unroll
        for (int kk = 0; kk < 2; kk++) {
            const uint32_t kboff = (uint32_t)kk * 4096u;
            uint32_t ah[2][4], bb[4][4];

            #pragma unroll
            for (int g = 0; g < 4; g++) {
                uint32_t bd = st + 8192u + kboff + bsel + brow16 + (uint32_t)g * 256u;
                LDSM_X4(bb[g][0], bb[g][1], bb[g][2], bb[g][3], bd);
            }
            #pragma unroll
            for (int mt = 0; mt < 2; mt++) {
                uint32_t ad = st + kboff + asel + arow16 + (uint32_t)mt * 256u;
                LDSM_X4(ah[mt][0], ah[mt][1], ah[mt][2], ah[mt][3], ad);
            }
            #pragma unroll
            for (int mt = 0; mt < 2; mt++)
                #pragma unroll
                for (int nt = 0; nt < 8; nt++) {
                    const int g = nt >> 1, hh = (nt & 1) * 2;
                    MMA_F16(acc[mt][nt], ah[mt], bb[g][hh], bb[g][hh + 1]);
                }
        }
    }

    const int r0    = lane >> 2;
    const int cpair = (lane & 3) * 2;
    #pragma unroll
    for (int mt = 0; mt < 2; mt++)
        #pragma unroll
        for (int nt = 0; nt < 8; nt++) {
            const int row = blockIdx.y * 128 + wm * 32 + mt * 16 + r0;
            const int col = blockIdx.x * 128 + wn * 64 + nt * 8 + cpair;
            #pragma unroll
            for (int h = 0; h < 2; h++) {
                const int rr = row + h * 8;
                const float v0 = acc[mt][nt][h * 2 + 0];
                const float v1 = acc[mt][nt][h * 2 + 1];
                const size_t o = (size_t)rr * Nstride + col;
                if (MODE == 0) {
                    __half2 hv;
                    hv.x = __float2half_rn(tanhf(v0));
                    hv.y = __float2half_rn(tanhf(v1));
                    *(__half2*)(outh + o) = hv;
                } else if (MODE == 1) {
                    const float2 bv = *(const float2*)(bias + col);
                    const float2 xf = __half22float2(*(const __half2*)(x0h + o));
                    const float2 lf = __half22float2(*(const __half2*)(xlh + o));
                    float2 ov;
                    ov.x = fmaf(xf.x, v0 + bv.x, lf.x);
                    ov.y = fmaf(xf.y, v1 + bv.y, lf.y);
                    *(float2*)(out + o) = ov;
                } else {
                    const float2 bv = *(const float2*)(bias + col);
                    const float2 xf = __half22float2(*(const __half2*)(x0h + o));
                    __half2 hv;
                    hv.x = __float2half_rn(xf.x * (1.0f + v0 + bv.x));
                    hv.y = __float2half_rn(xf.y * (1.0f + v1 + bv.y));
                    *(__half2*)(outh + o) = hv;
                }
            }
        }
}

// ---------------------------------------------------------------------------
extern "C" void kernel_launch(void* const* d_in, const int* in_sizes, int n_in,
                              void* d_out, int out_size)
{
    const float* x     = (const float*)d_in[0];
    const float* U     = (const float*)d_in[1];
    const float* V     = (const float*)d_in[2];
    const float* C     = (const float*)d_in[3];
    const float* bias  = (const float*)d_in[4];
    const float* gateW = (const float*)d_in[5];
    float* out = (float*)d_out;

    __half *w1h, *w2h, *xh, *x0h, *zh, *hh;
    cudaGetSymbolAddress((void**)&w1h,  g_W1h);
    cudaGetSymbolAddress((void**)&w2h,  g_W2h);
    cudaGetSymbolAddress((void**)&xh,   g_Xh);
    cudaGetSymbolAddress((void**)&x0h,  g_X0h);
    cudaGetSymbolAddress((void**)&zh,   g_Zh);
    cudaGetSymbolAddress((void**)&hh,   g_Hh);

    const int GEMM_SMEM = 5 * 16384;
    cudaFuncSetAttribute(mma_gemm<0, 1024>, cudaFuncAttributeMaxDynamicSharedMemorySize, GEMM_SMEM);
    cudaFuncSetAttribute(mma_gemm<1, 256>,  cudaFuncAttributeMaxDynamicSharedMemorySize, GEMM_SMEM);
    cudaFuncSetAttribute(mma_gemm<2, 256>,  cudaFuncAttributeMaxDynamicSharedMemorySize, GEMM_SMEM);

    repack_kernel<<<(L_NUM * N1 * D_DIM + 255) / 256, 256>>>(U, V);
    convert_x_kernel<<<B_ROWS * D_DIM / 4 / 256, 256>>>(x);

    for (int i = 0; i < L_NUM; i++) {
        const size_t woff = (size_t)i * N1 * D_DIM;
        const float* Cl = C + (size_t)i * E_NUM * R_DIM * R_DIM;
        const __half* xin = (i == 0) ? x0h : xh;

        // GEMM1: Hh = fp16(tanh(Xin @ W1^T))   [16384 x 256], K = 1024
        mma_gemm<0, 1024><<<dim3(2, B_ROWS / 128), 256, GEMM_SMEM>>>(
            xin, w1h + woff, nullptr, nullptr, nullptr, nullptr, hh, N1);

        // fused gate + middle -> Zh
        fused_mid<<<B_ROWS / 8, 256>>>(xin, gateW, Cl, hh, zh);

        // GEMM2  [16384 x 1024], K = 256
        if (i == 0) {
            // xh <- fp16(x0*(1 + Z@W2^T + bias))
            mma_gemm<2, 256><<<dim3(8, B_ROWS / 128), 256, GEMM_SMEM>>>(
                zh, w2h + woff, x0h, nullptr, bias, nullptr, xh, D_DIM);
        } else {
            // out = xh + x0*(Z@W2^T + bias)
            mma_gemm<1, 256><<<dim3(8, B_ROWS / 128), 256, GEMM_SMEM>>>(
                zh, w2h + woff, x0h, xh, bias + (size_t)i * D_DIM, out, nullptr, D_DIM);
        }
    }
}

// round 11
// speedup vs baseline: 1.2653x; 1.1972x over previous
#include <cuda_runtime.h>
#include <cuda_fp16.h>
#include <math.h>
#include <stdint.h>

#define B_ROWS 16384
#define D_DIM  1024
#define R_DIM  64
#define E_NUM  4
#define L_NUM  2
#define N1     256   // E * R

// ---------------------------------------------------------------------------
// Device scratch (all intermediates fp16)
// ---------------------------------------------------------------------------
__device__ __half g_W1h[L_NUM * N1 * D_DIM];   // [L][n=e*64+r][k=d]  fp16(V)
__device__ __half g_W2h[L_NUM * D_DIM * N1];   // [L][n=d][k=e*64+r]  fp16(U)
__device__ __half g_Cbd[L_NUM * N1 * N1];      // [L][n][k] block-diag fp16(C)
__device__ __half g_Xh [B_ROWS * D_DIM];       // fp16(x_l) after layer 0
__device__ __half g_X0h[B_ROWS * D_DIM];       // fp16(x0)
__device__ __half g_Zh [B_ROWS * N1];          // fp16(Z)
__device__ __half g_Hh [B_ROWS * N1];          // fp16(H)
__device__ float g_Gate[B_ROWS * E_NUM];

// ---------------------------------------------------------------------------
// Helpers
// ---------------------------------------------------------------------------
__device__ __forceinline__ uint32_t smem_u32(const void* p) {
    uint32_t a;
    asm("{ .reg .u64 t; cvta.to.shared.u64 t, %1; cvt.u32.u64 %0, t; }"
        : "=r"(a) : "l"(p));
    return a;
}

#define CP_ASYNC16(dst, src) \
    asm volatile("cp.async.cg.shared.global [%0], [%1], 16;" :: "r"(dst), "l"(src))
#define CP_COMMIT() asm volatile("cp.async.commit_group;" ::: "memory")
#define CP_WAIT3()  asm volatile("cp.async.wait_group 3;" ::: "memory")

#define LDSM_X4(r0, r1, r2, r3, addr) \
    asm volatile("ldmatrix.sync.aligned.m8n8.x4.shared.b16 {%0,%1,%2,%3}, [%4];" \
        : "=r"(r0), "=r"(r1), "=r"(r2), "=r"(r3) : "r"(addr))

#define MMA_F16(d, a, b0, b1) \
    asm volatile("mma.sync.aligned.m16n8k16.row.col.f32.f16.f16.f32 " \
        "{%0,%1,%2,%3}, {%4,%5,%6,%7}, {%8,%9}, {%0,%1,%2,%3};" \
        : "+f"((d)[0]), "+f"((d)[1]), "+f"((d)[2]), "+f"((d)[3]) \
        : "r"((a)[0]), "r"((a)[1]), "r"((a)[2]), "r"((a)[3]), "r"(b0), "r"(b1))

// ---------------------------------------------------------------------------
// Weight repacks (fp16)
// ---------------------------------------------------------------------------
__global__ void repack_kernel(const float* __restrict__ U, const float* __restrict__ V) {
    int idx = blockIdx.x * blockDim.x + threadIdx.x;
    const int per = N1 * D_DIM;
    if (idx >= L_NUM * per) return;
    int i   = idx / per;
    int rem = idx - i * per;
    {   // W1[n][k] = V[i, e=n>>6, d=k, r=n&63]
        int n = rem / D_DIM, k = rem - (rem / D_DIM) * D_DIM;
        float v = V[(((size_t)i * E_NUM + (n >> 6)) * D_DIM + k) * R_DIM + (n & 63)];
        g_W1h[idx] = __float2half_rn(v);
    }
    {   // W2[d][k2] = U[i, e=k2>>6, d, r=k2&63]
        int d = rem / N1, k2 = rem - (rem / N1) * N1;
        float u = U[(((size_t)i * E_NUM + (k2 >> 6)) * D_DIM + d) * R_DIM + (k2 & 63)];
        g_W2h[(size_t)i * D_DIM * N1 + rem] = __float2half_rn(u);
    }
}

// Cbd[i][n][k] = C[i, e=n>>6, r=n&63, q=k&63] if (k>>6)==e else 0
__global__ void repack_c_kernel(const float* __restrict__ C) {
    int idx = blockIdx.x * blockDim.x + threadIdx.x;
    if (idx >= L_NUM * N1 * N1) return;
    int i   = idx / (N1 * N1);
    int rem = idx - i * (N1 * N1);
    int n = rem >> 8, k = rem & 255;
    int e = n >> 6;
    float v = ((k >> 6) == e)
        ? C[(((size_t)i * E_NUM + e) * R_DIM + (n & 63)) * R_DIM + (k & 63)]
        : 0.0f;
    g_Cbd[idx] = __float2half_rn(v);
}

__global__ void convert_x_kernel(const float* __restrict__ x) {
    int i = (blockIdx.x * 256 + threadIdx.x) * 4;
    float4 v = *(const float4*)(x + i);
    __half2 h01, h23;
    h01.x = __float2half_rn(v.x); h01.y = __float2half_rn(v.y);
    h23.x = __float2half_rn(v.z); h23.y = __float2half_rn(v.w);
    *(__half2*)(g_X0h + i)     = h01;
    *(__half2*)(g_X0h + i + 2) = h23;
}

// ---------------------------------------------------------------------------
// Gate kernel: 16 rows/block, warp handles 2 rows interleaved (MLP ~8).
// ---------------------------------------------------------------------------
__global__ void __launch_bounds__(256)
gate_kernel(const __half* __restrict__ Xh, const float* __restrict__ gateW,
            float* __restrict__ gate)
{
    __shared__ float sG[E_NUM * D_DIM];
    const int tid = threadIdx.x;
    #pragma unroll
    for (int i = tid * 4; i < E_NUM * D_DIM; i += 1024)
        *(float4*)(sG + i) = *(const float4*)(gateW + i);
    __syncthreads();

    const int warp = tid >> 5, lane = tid & 31;
    const int b = blockIdx.x * 16 + warp * 2;
    const __half* xr0 = Xh + (size_t)b * D_DIM;
    const __half* xr1 = xr0 + D_DIM;

    // preload both rows, all 4 chunks (8 uint4 in flight)
    uint4 xv[2][4];
    #pragma unroll
    for (int j = 0; j < 4; j++) {
        const int off = lane * 8 + j * 256;
        xv[0][j] = *(const uint4*)(xr0 + off);
        xv[1][j] = *(const uint4*)(xr1 + off);
    }

    float acc[2][4];
    #pragma unroll
    for (int r = 0; r < 2; r++)
        #pragma unroll
        for (int e = 0; e < 4; e++) acc[r][e] = 0.0f;

    #pragma unroll
    for (int j = 0; j < 4; j++) {
        const int off = lane * 8 + j * 256;
        float2 xf[2][4];
        #pragma unroll
        for (int r = 0; r < 2; r++) {
            xf[r][0] = __half22float2(*(__half2*)&xv[r][j].x);
            xf[r][1] = __half22float2(*(__half2*)&xv[r][j].y);
            xf[r][2] = __half22float2(*(__half2*)&xv[r][j].z);
            xf[r][3] = __half22float2(*(__half2*)&xv[r][j].w);
        }
        #pragma unroll
        for (int e = 0; e < 4; e++) {
            float4 ga = *(const float4*)(sG + e * D_DIM + off);
            float4 gb = *(const float4*)(sG + e * D_DIM + off + 4);
            #pragma unroll
            for (int r = 0; r < 2; r++) {
                acc[r][e] += xf[r][0].x * ga.x + xf[r][0].y * ga.y
                           + xf[r][1].x * ga.z + xf[r][1].y * ga.w
                           + xf[r][2].x * gb.x + xf[r][2].y * gb.y
                           + xf[r][3].x * gb.z + xf[r][3].y * gb.w;
            }
        }
    }
    #pragma unroll
    for (int r = 0; r < 2; r++)
        #pragma unroll
        for (int e = 0; e < 4; e++)
            #pragma unroll
            for (int o = 16; o > 0; o >>= 1)
                acc[r][e] += __shfl_xor_sync(0xffffffffu, acc[r][e], o);

    if (lane < 2) {
        const int r = lane;
        float a0 = acc[r][0], a1 = acc[r][1], a2 = acc[r][2], a3 = acc[r][3];
        float mx = fmaxf(fmaxf(a0, a1), fmaxf(a2, a3));
        float e0 = expf(a0 - mx), e1 = expf(a1 - mx);
        float e2 = expf(a2 - mx), e3 = expf(a3 - mx);
        float inv = 1.0f / (e0 + e1 + e2 + e3);
        float4 g = make_float4(e0 * inv, e1 * inv, e2 * inv, e3 * inv);
        *(float4*)(gate + (size_t)(b + r) * 4) = g;
    }
}

// ---------------------------------------------------------------------------
// Stage loader: 2 arrays (A, B), each 128 rows x 32 k (fp16) = 8KB.
// ---------------------------------------------------------------------------
template<int KDIM>
__device__ __forceinline__ void load_stage(
    uint32_t sbase,
    const __half* __restrict__ A, const __half* __restrict__ B,
    int k0, int tid)
{
    #pragma unroll
    for (int h = 0; h < 2; h++) {
        int c   = tid + h * 256;       // 0..511
        int row = c >> 2;
        int kb  = c & 3;
        size_t   go = (size_t)row * KDIM + k0 + kb * 8;
        uint32_t so = (uint32_t)(kb * 2048 + row * 16);
        CP_ASYNC16(sbase +         so, A + go);
        CP_ASYNC16(sbase + 8192u + so, B + go);
    }
}

// ---------------------------------------------------------------------------
// fp16 mma GEMM: BM=128, BN=128, BK=32, 8 warps (4m x 2n), 5-stage pipeline.
// MODE 0: outh = fp16(tanh(A@B))                         (GEMM1 -> H)
// MODE 1: out  = xlh + x0h*(A@B + bias)                  (GEMM2 final, fp32)
// MODE 2: outh = fp16(x0h*(1 + A@B + bias))              (GEMM2 layer-0)
// MODE 3: outh = fp16(gate[row,e]*tanh(A@B)), e=col>>6   (ZGEMM)
// ---------------------------------------------------------------------------
template<int MODE, int KDIM>
__global__ void __launch_bounds__(256, 2)
mma_gemm(const __half* __restrict__ Ag, const __half* __restrict__ Bg,
         const __half* __restrict__ x0h, const __half* __restrict__ xlh,
         const float* __restrict__ bias, const float* __restrict__ gate,
         float* __restrict__ out, __half* __restrict__ outh, int Nstride)
{
    constexpr int BK = 32, NK = KDIM / BK, NST = 5;
    constexpr uint32_t STAGE = 16384u;
    extern __shared__ char smem[];
    const uint32_t sbase = smem_u32(smem);

    const int tid  = threadIdx.x;
    const int wid  = tid >> 5;
    const int lane = tid & 31;
    const int wm   = wid & 3;
    const int wn   = wid >> 2;

    const __half* A = Ag + (size_t)blockIdx.y * 128 * KDIM;
    const __half* B = Bg + (size_t)blockIdx.x * 128 * KDIM;

    float acc[2][8][4];
    #pragma unroll
    for (int a = 0; a < 2; a++)
        #pragma unroll
        for (int b = 0; b < 8; b++)
            #pragma unroll
            for (int c = 0; c < 4; c++) acc[a][b][c] = 0.0f;

    #pragma unroll
    for (int p = 0; p < 4 && p < NK; p++) {
        load_stage<KDIM>(sbase + (uint32_t)p * STAGE, A, B, p * BK, tid);
        CP_COMMIT();
    }

    const uint32_t arow16 = (uint32_t)((wm * 32 + (lane & 15)) * 16);
    const uint32_t asel   = (uint32_t)(lane >> 4) * 2048u;
    const uint32_t brow16 = (uint32_t)((wn * 64 + (lane & 7) + ((lane >> 4) << 3)) * 16);
    const uint32_t bsel   = (uint32_t)((lane >> 3) & 1) * 2048u;

    for (int i = 0; i < NK; i++) {
        CP_WAIT3();
        __syncthreads();
        if (i + 4 < NK) {
            load_stage<KDIM>(sbase + (uint32_t)((i + 4) % NST) * STAGE,
                             A, B, (i + 4) * BK, tid);
        }
        CP_COMMIT();

        const uint32_t st = sbase + (uint32_t)(i % NST) * STAGE;
        #pragma unroll
        for (int kk = 0; kk < 2; kk++) {
            const uint32_t kboff = (uint32_t)kk * 4096u;
            uint32_t ah[2][4], bb[4][4];

            #pragma unroll
            for (int g = 0; g < 4; g++) {
                uint32_t bd = st + 8192u + kboff + bsel + brow16 + (uint32_t)g * 256u;
                LDSM_X4(bb[g][0], bb[g][1], bb[g][2], bb[g][3], bd);
            }
            #pragma unroll
            for (int mt = 0; mt < 2; mt++) {
                uint32_t ad = st + kboff + asel + arow16 + (uint32_t)mt * 256u;
                LDSM_X4(ah[mt][0], ah[mt][1], ah[mt][2], ah[mt][3], ad);
            }
            #pragma unroll
            for (int mt = 0; mt < 2; mt++)
                #pragma unroll
                for (int nt = 0; nt < 8; nt++) {
                    const int g = nt >> 1, hh = (nt & 1) * 2;
                    MMA_F16(acc[mt][nt], ah[mt], bb[g][hh], bb[g][hh + 1]);
                }
        }
    }

    const int r0    = lane >> 2;
    const int cpair = (lane & 3) * 2;
    #pragma unroll
    for (int mt = 0; mt < 2; mt++)
        #pragma unroll
        for (int nt = 0; nt < 8; nt++) {
            const int row = blockIdx.y * 128 + wm * 32 + mt * 16 + r0;
            const int col = blockIdx.x * 128 + wn * 64 + nt * 8 + cpair;
            #pragma unroll
            for (int h = 0; h < 2; h++) {
                const int rr = row + h * 8;
                const float v0 = acc[mt][nt][h * 2 + 0];
                const float v1 = acc[mt][nt][h * 2 + 1];
                const size_t o = (size_t)rr * Nstride + col;
                if (MODE == 0) {
                    __half2 hv;
                    hv.x = __float2half_rn(tanhf(v0));
                    hv.y = __float2half_rn(tanhf(v1));
                    *(__half2*)(outh + o) = hv;
                } else if (MODE == 1) {
                    const float2 bv = *(const float2*)(bias + col);
                    const float2 xf = __half22float2(*(const __half2*)(x0h + o));
                    const float2 lf = __half22float2(*(const __half2*)(xlh + o));
                    float2 ov;
                    ov.x = fmaf(xf.x, v0 + bv.x, lf.x);
                    ov.y = fmaf(xf.y, v1 + bv.y, lf.y);
                    *(float2*)(out + o) = ov;
                } else if (MODE == 2) {
                    const float2 bv = *(const float2*)(bias + col);
                    const float2 xf = __half22float2(*(const __half2*)(x0h + o));
                    __half2 hv;
                    hv.x = __float2half_rn(xf.x * (1.0f + v0 + bv.x));
                    hv.y = __float2half_rn(xf.y * (1.0f + v1 + bv.y));
                    *(__half2*)(outh + o) = hv;
                } else {
                    const int e = (col >> 6) & 3;
                    const float g = gate[(size_t)rr * 4 + e];
                    __half2 hv;
                    hv.x = __float2half_rn(g * tanhf(v0));
                    hv.y = __float2half_rn(g * tanhf(v1));
                    *(__half2*)(outh + o) = hv;
                }
            }
        }
}

// ---------------------------------------------------------------------------
extern "C" void kernel_launch(void* const* d_in, const int* in_sizes, int n_in,
                              void* d_out, int out_size)
{
    const float* x     = (const float*)d_in[0];
    const float* U     = (const float*)d_in[1];
    const float* V     = (const float*)d_in[2];
    const float* C     = (const float*)d_in[3];
    const float* bias  = (const float*)d_in[4];
    const float* gateW = (const float*)d_in[5];
    float* out = (float*)d_out;

    __half *w1h, *w2h, *cbd, *xh, *x0h, *zh, *hh;
    float *gbuf;
    cudaGetSymbolAddress((void**)&w1h,  g_W1h);
    cudaGetSymbolAddress((void**)&w2h,  g_W2h);
    cudaGetSymbolAddress((void**)&cbd,  g_Cbd);
    cudaGetSymbolAddress((void**)&xh,   g_Xh);
    cudaGetSymbolAddress((void**)&x0h,  g_X0h);
    cudaGetSymbolAddress((void**)&zh,   g_Zh);
    cudaGetSymbolAddress((void**)&hh,   g_Hh);
    cudaGetSymbolAddress((void**)&gbuf, g_Gate);

    const int GEMM_SMEM = 5 * 16384;
    cudaFuncSetAttribute(mma_gemm<0, 1024>, cudaFuncAttributeMaxDynamicSharedMemorySize, GEMM_SMEM);
    cudaFuncSetAttribute(mma_gemm<1, 256>,  cudaFuncAttributeMaxDynamicSharedMemorySize, GEMM_SMEM);
    cudaFuncSetAttribute(mma_gemm<2, 256>,  cudaFuncAttributeMaxDynamicSharedMemorySize, GEMM_SMEM);
    cudaFuncSetAttribute(mma_gemm<3, 256>,  cudaFuncAttributeMaxDynamicSharedMemorySize, GEMM_SMEM);

    repack_kernel<<<(L_NUM * N1 * D_DIM + 255) / 256, 256>>>(U, V);
    repack_c_kernel<<<(L_NUM * N1 * N1 + 255) / 256, 256>>>(C);
    convert_x_kernel<<<B_ROWS * D_DIM / 4 / 256, 256>>>(x);

    for (int i = 0; i < L_NUM; i++) {
        const size_t woff = (size_t)i * N1 * D_DIM;
        const __half* xin = (i == 0) ? x0h : xh;

        // GEMM1: Hh = fp16(tanh(Xin @ W1^T))   [16384 x 256], K = 1024
        mma_gemm<0, 1024><<<dim3(2, B_ROWS / 128), 256, GEMM_SMEM>>>(
            xin, w1h + woff, nullptr, nullptr, nullptr, nullptr, nullptr, hh, N1);

        // gate logits + softmax
        gate_kernel<<<B_ROWS / 16, 256>>>(xin, gateW, gbuf);

        // ZGEMM: Zh = fp16(gate * tanh(H @ Cbd^T))  [16384 x 256], K = 256
        mma_gemm<3, 256><<<dim3(2, B_ROWS / 128), 256, GEMM_SMEM>>>(
            hh, cbd + (size_t)i * N1 * N1, nullptr, nullptr, nullptr, gbuf,
            nullptr, zh, N1);

        // GEMM2  [16384 x 1024], K = 256
        if (i == 0) {
            mma_gemm<2, 256><<<dim3(8, B_ROWS / 128), 256, GEMM_SMEM>>>(
                zh, w2h + woff, x0h, nullptr, bias, nullptr, nullptr, xh, D_DIM);
        } else {
            mma_gemm<1, 256><<<dim3(8, B_ROWS / 128), 256, GEMM_SMEM>>>(
                zh, w2h + woff, x0h, xh, bias + (size_t)i * D_DIM, nullptr, out, nullptr, D_DIM);
        }
    }
}

// round 12
// speedup vs baseline: 1.3406x; 1.0595x over previous
#include <cuda_runtime.h>
#include <cuda_fp16.h>
#include <math.h>
#include <stdint.h>

#define B_ROWS 16384
#define D_DIM  1024
#define R_DIM  64
#define E_NUM  4
#define L_NUM  2
#define N1     256   // E * R

// ---------------------------------------------------------------------------
// Device scratch (all intermediates fp16)
// ---------------------------------------------------------------------------
__device__ __half g_W1h[L_NUM * N1 * D_DIM];   // [L][n=e*64+r][k=d]  fp16(V)
__device__ __half g_W2h[L_NUM * D_DIM * N1];   // [L][n=d][k=e*64+r]  fp16(U)
__device__ __half g_Cq [L_NUM * E_NUM * R_DIM * R_DIM];  // fp16(C), native layout
__device__ __half g_Xh [B_ROWS * D_DIM];       // fp16(x_l) after layer 0
__device__ __half g_X0h[B_ROWS * D_DIM];       // fp16(x0)
__device__ __half g_Zh [B_ROWS * N1];          // fp16(Z)
__device__ __half g_Hh [B_ROWS * N1];          // fp16(H)
__device__ float g_Gate[B_ROWS * E_NUM];

// ---------------------------------------------------------------------------
// Helpers
// ---------------------------------------------------------------------------
__device__ __forceinline__ uint32_t smem_u32(const void* p) {
    uint32_t a;
    asm("{ .reg .u64 t; cvta.to.shared.u64 t, %1; cvt.u32.u64 %0, t; }"
        : "=r"(a) : "l"(p));
    return a;
}

#define CP_ASYNC16(dst, src) \
    asm volatile("cp.async.cg.shared.global [%0], [%1], 16;" :: "r"(dst), "l"(src))
#define CP_COMMIT() asm volatile("cp.async.commit_group;" ::: "memory")
#define CP_WAIT3()  asm volatile("cp.async.wait_group 3;" ::: "memory")
#define CP_WAIT0()  asm volatile("cp.async.wait_group 0;" ::: "memory")

#define LDSM_X4(r0, r1, r2, r3, addr) \
    asm volatile("ldmatrix.sync.aligned.m8n8.x4.shared.b16 {%0,%1,%2,%3}, [%4];" \
        : "=r"(r0), "=r"(r1), "=r"(r2), "=r"(r3) : "r"(addr))

#define MMA_F16(d, a, b0, b1) \
    asm volatile("mma.sync.aligned.m16n8k16.row.col.f32.f16.f16.f32 " \
        "{%0,%1,%2,%3}, {%4,%5,%6,%7}, {%8,%9}, {%0,%1,%2,%3};" \
        : "+f"((d)[0]), "+f"((d)[1]), "+f"((d)[2]), "+f"((d)[3]) \
        : "r"((a)[0]), "r"((a)[1]), "r"((a)[2]), "r"((a)[3]), "r"(b0), "r"(b1))

// ---------------------------------------------------------------------------
// W1 repack with 64x64 smem transpose (coalesced both sides)
// W1[i][n=e*64+r][k=d] = V[i,e,d,r]
// grid: L*E*(D/64) blocks of 256
// ---------------------------------------------------------------------------
__global__ void repack_w1_kernel(const float* __restrict__ V) {
    __shared__ float tile[64][65];
    const int blk  = blockIdx.x;
    const int dblk = blk & 15;          // D/64 = 16
    const int e    = (blk >> 4) & 3;
    const int i    = blk >> 6;
    const int tid  = threadIdx.x;

    const float* src = V + (((size_t)i * E_NUM + e) * D_DIM + dblk * 64) * R_DIM;
    #pragma unroll
    for (int it = 0; it < 16; it++) {
        int lin = tid + it * 256;
        int dr = lin >> 6, rr = lin & 63;
        tile[dr][rr] = src[dr * 64 + rr];
    }
    __syncthreads();
    __half* dst = g_W1h + ((size_t)i * N1 + e * 64) * D_DIM + dblk * 64;
    #pragma unroll
    for (int it = 0; it < 16; it++) {
        int lin = tid + it * 256;
        int rr = lin >> 6, dr = lin & 63;
        dst[(size_t)rr * D_DIM + dr] = __float2half_rn(tile[dr][rr]);
    }
}

// W2[i][d][k2=e*64+r] = U[i,e,d,r]  — coalesced both sides when k2 fastest
__global__ void repack_w2_kernel(const float* __restrict__ U) {
    int idx = blockIdx.x * blockDim.x + threadIdx.x;
    if (idx >= L_NUM * D_DIM * N1) return;
    int i   = idx / (D_DIM * N1);
    int rem = idx - i * (D_DIM * N1);
    int d = rem >> 8, k2 = rem & 255;
    int e = k2 >> 6, r = k2 & 63;
    g_W2h[idx] = __float2half_rn(U[(((size_t)i * E_NUM + e) * D_DIM + d) * R_DIM + r]);
}

// Cq: straight fp16 convert (native [L][E][r][q] layout IS the K-major B tile)
__global__ void repack_c_kernel(const float* __restrict__ C) {
    int idx = blockIdx.x * blockDim.x + threadIdx.x;
    if (idx < L_NUM * E_NUM * R_DIM * R_DIM)
        g_Cq[idx] = __float2half_rn(C[idx]);
}

__global__ void convert_x_kernel(const float* __restrict__ x) {
    int i = (blockIdx.x * 256 + threadIdx.x) * 4;
    float4 v = *(const float4*)(x + i);
    __half2 h01, h23;
    h01.x = __float2half_rn(v.x); h01.y = __float2half_rn(v.y);
    h23.x = __float2half_rn(v.z); h23.y = __float2half_rn(v.w);
    *(__half2*)(g_X0h + i)     = h01;
    *(__half2*)(g_X0h + i + 2) = h23;
}

// ---------------------------------------------------------------------------
// Gate kernel: 16 rows/block, warp handles 2 rows interleaved.
// ---------------------------------------------------------------------------
__global__ void __launch_bounds__(256)
gate_kernel(const __half* __restrict__ Xh, const float* __restrict__ gateW,
            float* __restrict__ gate)
{
    __shared__ float sG[E_NUM * D_DIM];
    const int tid = threadIdx.x;
    #pragma unroll
    for (int i = tid * 4; i < E_NUM * D_DIM; i += 1024)
        *(float4*)(sG + i) = *(const float4*)(gateW + i);
    __syncthreads();

    const int warp = tid >> 5, lane = tid & 31;
    const int b = blockIdx.x * 16 + warp * 2;
    const __half* xr0 = Xh + (size_t)b * D_DIM;
    const __half* xr1 = xr0 + D_DIM;

    uint4 xv[2][4];
    #pragma unroll
    for (int j = 0; j < 4; j++) {
        const int off = lane * 8 + j * 256;
        xv[0][j] = *(const uint4*)(xr0 + off);
        xv[1][j] = *(const uint4*)(xr1 + off);
    }

    float acc[2][4];
    #pragma unroll
    for (int r = 0; r < 2; r++)
        #pragma unroll
        for (int e = 0; e < 4; e++) acc[r][e] = 0.0f;

    #pragma unroll
    for (int j = 0; j < 4; j++) {
        const int off = lane * 8 + j * 256;
        float2 xf[2][4];
        #pragma unroll
        for (int r = 0; r < 2; r++) {
            xf[r][0] = __half22float2(*(__half2*)&xv[r][j].x);
            xf[r][1] = __half22float2(*(__half2*)&xv[r][j].y);
            xf[r][2] = __half22float2(*(__half2*)&xv[r][j].z);
            xf[r][3] = __half22float2(*(__half2*)&xv[r][j].w);
        }
        #pragma unroll
        for (int e = 0; e < 4; e++) {
            float4 ga = *(const float4*)(sG + e * D_DIM + off);
            float4 gb = *(const float4*)(sG + e * D_DIM + off + 4);
            #pragma unroll
            for (int r = 0; r < 2; r++) {
                acc[r][e] += xf[r][0].x * ga.x + xf[r][0].y * ga.y
                           + xf[r][1].x * ga.z + xf[r][1].y * ga.w
                           + xf[r][2].x * gb.x + xf[r][2].y * gb.y
                           + xf[r][3].x * gb.z + xf[r][3].y * gb.w;
            }
        }
    }
    #pragma unroll
    for (int r = 0; r < 2; r++)
        #pragma unroll
        for (int e = 0; e < 4; e++)
            #pragma unroll
            for (int o = 16; o > 0; o >>= 1)
                acc[r][e] += __shfl_xor_sync(0xffffffffu, acc[r][e], o);

    if (lane < 2) {
        const int r = lane;
        float a0 = acc[r][0], a1 = acc[r][1], a2 = acc[r][2], a3 = acc[r][3];
        float mx = fmaxf(fmaxf(a0, a1), fmaxf(a2, a3));
        float e0 = expf(a0 - mx), e1 = expf(a1 - mx);
        float e2 = expf(a2 - mx), e3 = expf(a3 - mx);
        float inv = 1.0f / (e0 + e1 + e2 + e3);
        float4 g = make_float4(e0 * inv, e1 * inv, e2 * inv, e3 * inv);
        *(float4*)(gate + (size_t)(b + r) * 4) = g;
    }
}

// ---------------------------------------------------------------------------
// Block-diagonal ZGEMM: grid (E_NUM, B_ROWS/128).
// Z[row, e*64+n] = fp16(gate[row,e] * tanh(sum_q H[row, e*64+q] * C[e][n][q]))
// BM=128, BN=64, K=64. Single-shot smem (24KB), 8 warps (4m x 2n), warp 32x32.
// ---------------------------------------------------------------------------
__global__ void __launch_bounds__(256)
zgemm_bd(const __half* __restrict__ Hh, const __half* __restrict__ Cq,
         const float* __restrict__ gate, __half* __restrict__ Zh)
{
    extern __shared__ char smem[];
    const uint32_t sbase = smem_u32(smem);       // A: 16KB (8 panels x 128x16B)
    const uint32_t bbase = sbase + 16384u;       // B:  8KB (8 panels x 64x16B)

    const int tid  = threadIdx.x;
    const int wid  = tid >> 5;
    const int lane = tid & 31;
    const int wm   = wid & 3;
    const int wn   = wid >> 2;
    const int e    = blockIdx.x;

    const __half* A = Hh + (size_t)blockIdx.y * 128 * N1 + e * 64;
    const __half* B = Cq + (size_t)e * 64 * 64;

    // load A: 128 rows x 8 kb-panels = 1024 chunks of 16B, 4/thread
    #pragma unroll
    for (int h = 0; h < 4; h++) {
        int c = tid + h * 256;
        int row = c >> 3, kb = c & 7;
        CP_ASYNC16(sbase + (uint32_t)(kb * 2048 + row * 16),
                   A + (size_t)row * N1 + kb * 8);
    }
    // load B: 64 rows x 8 kb = 512 chunks, 2/thread
    #pragma unroll
    for (int h = 0; h < 2; h++) {
        int c = tid + h * 256;
        int row = c >> 3, kb = c & 7;
        CP_ASYNC16(bbase + (uint32_t)(kb * 1024 + row * 16),
                   B + (size_t)row * 64 + kb * 8);
    }
    CP_COMMIT();
    CP_WAIT0();
    __syncthreads();

    float acc[2][4][4];
    #pragma unroll
    for (int a = 0; a < 2; a++)
        #pragma unroll
        for (int b2 = 0; b2 < 4; b2++)
            #pragma unroll
            for (int c = 0; c < 4; c++) acc[a][b2][c] = 0.0f;

    const uint32_t arow16 = (uint32_t)((wm * 32 + (lane & 15)) * 16);
    const uint32_t asel   = (uint32_t)(lane >> 4) * 2048u;
    const uint32_t brow16 = (uint32_t)((wn * 32 + (lane & 7) + ((lane >> 4) << 3)) * 16);
    const uint32_t bsel   = (uint32_t)((lane >> 3) & 1) * 1024u;

    #pragma unroll
    for (int kk = 0; kk < 4; kk++) {
        uint32_t ah[2][4], bb[2][4];
        #pragma unroll
        for (int g = 0; g < 2; g++) {
            uint32_t bd = bbase + (uint32_t)(kk * 2048) + bsel + brow16 + (uint32_t)g * 256u;
            LDSM_X4(bb[g][0], bb[g][1], bb[g][2], bb[g][3], bd);
        }
        #pragma unroll
        for (int mt = 0; mt < 2; mt++) {
            uint32_t ad = sbase + (uint32_t)(kk * 4096) + asel + arow16 + (uint32_t)mt * 256u;
            LDSM_X4(ah[mt][0], ah[mt][1], ah[mt][2], ah[mt][3], ad);
        }
        #pragma unroll
        for (int mt = 0; mt < 2; mt++)
            #pragma unroll
            for (int nt = 0; nt < 4; nt++) {
                const int g = nt >> 1, hh = (nt & 1) * 2;
                MMA_F16(acc[mt][nt], ah[mt], bb[g][hh], bb[g][hh + 1]);
            }
    }

    const int r0    = lane >> 2;
    const int cpair = (lane & 3) * 2;
    #pragma unroll
    for (int mt = 0; mt < 2; mt++)
        #pragma unroll
        for (int nt = 0; nt < 4; nt++) {
            const int row = blockIdx.y * 128 + wm * 32 + mt * 16 + r0;
            const int col = wn * 32 + nt * 8 + cpair;     // within expert block
            #pragma unroll
            for (int h = 0; h < 2; h++) {
                const int rr = row + h * 8;
                const float g = gate[(size_t)rr * 4 + e];
                __half2 hv;
                hv.x = __float2half_rn(g * tanhf(acc[mt][nt][h * 2 + 0]));
                hv.y = __float2half_rn(g * tanhf(acc[mt][nt][h * 2 + 1]));
                *(__half2*)(Zh + (size_t)rr * N1 + e * 64 + col) = hv;
            }
        }
}

// ---------------------------------------------------------------------------
// Stage loader: 2 arrays (A, B), each 128 rows x 32 k (fp16) = 8KB.
// ---------------------------------------------------------------------------
template<int KDIM>
__device__ __forceinline__ void load_stage(
    uint32_t sbase,
    const __half* __restrict__ A, const __half* __restrict__ B,
    int k0, int tid)
{
    #pragma unroll
    for (int h = 0; h < 2; h++) {
        int c   = tid + h * 256;       // 0..511
        int row = c >> 2;
        int kb  = c & 3;
        size_t   go = (size_t)row * KDIM + k0 + kb * 8;
        uint32_t so = (uint32_t)(kb * 2048 + row * 16);
        CP_ASYNC16(sbase +         so, A + go);
        CP_ASYNC16(sbase + 8192u + so, B + go);
    }
}

// ---------------------------------------------------------------------------
// fp16 mma GEMM: BM=128, BN=128, BK=32, 8 warps (4m x 2n), 5-stage pipeline.
// MODE 0: outh = fp16(tanh(A@B))                         (GEMM1 -> H)
// MODE 1: out  = xlh + x0h*(A@B + bias)                  (GEMM2 final, fp32)
// MODE 2: outh = fp16(x0h*(1 + A@B + bias))              (GEMM2 layer-0)
// ---------------------------------------------------------------------------
template<int MODE, int KDIM>
__global__ void __launch_bounds__(256, 2)
mma_gemm(const __half* __restrict__ Ag, const __half* __restrict__ Bg,
         const __half* __restrict__ x0h, const __half* __restrict__ xlh,
         const float* __restrict__ bias,
         float* __restrict__ out, __half* __restrict__ outh, int Nstride)
{
    constexpr int BK = 32, NK = KDIM / BK, NST = 5;
    constexpr uint32_t STAGE = 16384u;
    extern __shared__ char smem[];
    const uint32_t sbase = smem_u32(smem);

    const int tid  = threadIdx.x;
    const int wid  = tid >> 5;
    const int lane = tid & 31;
    const int wm   = wid & 3;
    const int wn   = wid >> 2;

    const __half* A = Ag + (size_t)blockIdx.y * 128 * KDIM;
    const __half* B = Bg + (size_t)blockIdx.x * 128 * KDIM;

    float acc[2][8][4];
    #pragma unroll
    for (int a = 0; a < 2; a++)
        #pragma unroll
        for (int b = 0; b < 8; b++)
            #pragma unroll
            for (int c = 0; c < 4; c++) acc[a][b][c] = 0.0f;

    #pragma unroll
    for (int p = 0; p < 4 && p < NK; p++) {
        load_stage<KDIM>(sbase + (uint32_t)p * STAGE, A, B, p * BK, tid);
        CP_COMMIT();
    }

    const uint32_t arow16 = (uint32_t)((wm * 32 + (lane & 15)) * 16);
    const uint32_t asel   = (uint32_t)(lane >> 4) * 2048u;
    const uint32_t brow16 = (uint32_t)((wn * 64 + (lane & 7) + ((lane >> 4) << 3)) * 16);
    const uint32_t bsel   = (uint32_t)((lane >> 3) & 1) * 2048u;

    for (int i = 0; i < NK; i++) {
        CP_WAIT3();
        __syncthreads();
        if (i + 4 < NK) {
            load_stage<KDIM>(sbase + (uint32_t)((i + 4) % NST) * STAGE,
                             A, B, (i + 4) * BK, tid);
        }
        CP_COMMIT();

        const uint32_t st = sbase + (uint32_t)(i % NST) * STAGE;
        #pragma unroll
        for (int kk = 0; kk < 2; kk++) {
            const uint32_t kboff = (uint32_t)kk * 4096u;
            uint32_t ah[2][4], bb[4][4];

            #pragma unroll
            for (int g = 0; g < 4; g++) {
                uint32_t bd = st + 8192u + kboff + bsel + brow16 + (uint32_t)g * 256u;
                LDSM_X4(bb[g][0], bb[g][1], bb[g][2], bb[g][3], bd);
            }
            #pragma unroll
            for (int mt = 0; mt < 2; mt++) {
                uint32_t ad = st + kboff + asel + arow16 + (uint32_t)mt * 256u;
                LDSM_X4(ah[mt][0], ah[mt][1], ah[mt][2], ah[mt][3], ad);
            }
            #pragma unroll
            for (int mt = 0; mt < 2; mt++)
                #pragma unroll
                for (int nt = 0; nt < 8; nt++) {
                    const int g = nt >> 1, hh = (nt & 1) * 2;
                    MMA_F16(acc[mt][nt], ah[mt], bb[g][hh], bb[g][hh + 1]);
                }
        }
    }

    const int r0    = lane >> 2;
    const int cpair = (lane & 3) * 2;
    #pragma unroll
    for (int mt = 0; mt < 2; mt++)
        #pragma unroll
        for (int nt = 0; nt < 8; nt++) {
            const int row = blockIdx.y * 128 + wm * 32 + mt * 16 + r0;
            const int col = blockIdx.x * 128 + wn * 64 + nt * 8 + cpair;
            #pragma unroll
            for (int h = 0; h < 2; h++) {
                const int rr = row + h * 8;
                const float v0 = acc[mt][nt][h * 2 + 0];
                const float v1 = acc[mt][nt][h * 2 + 1];
                const size_t o = (size_t)rr * Nstride + col;
                if (MODE == 0) {
                    __half2 hv;
                    hv.x = __float2half_rn(tanhf(v0));
                    hv.y = __float2half_rn(tanhf(v1));
                    *(__half2*)(outh + o) = hv;
                } else if (MODE == 1) {
                    const float2 bv = *(const float2*)(bias + col);
                    const float2 xf = __half22float2(*(const __half2*)(x0h + o));
                    const float2 lf = __half22float2(*(const __half2*)(xlh + o));
                    float2 ov;
                    ov.x = fmaf(xf.x, v0 + bv.x, lf.x);
                    ov.y = fmaf(xf.y, v1 + bv.y, lf.y);
                    *(float2*)(out + o) = ov;
                } else {
                    const float2 bv = *(const float2*)(bias + col);
                    const float2 xf = __half22float2(*(const __half2*)(x0h + o));
                    __half2 hv;
                    hv.x = __float2half_rn(xf.x * (1.0f + v0 + bv.x));
                    hv.y = __float2half_rn(xf.y * (1.0f + v1 + bv.y));
                    *(__half2*)(outh + o) = hv;
                }
            }
        }
}

// ---------------------------------------------------------------------------
extern "C" void kernel_launch(void* const* d_in, const int* in_sizes, int n_in,
                              void* d_out, int out_size)
{
    const float* x     = (const float*)d_in[0];
    const float* U     = (const float*)d_in[1];
    const float* V     = (const float*)d_in[2];
    const float* C     = (const float*)d_in[3];
    const float* bias  = (const float*)d_in[4];
    const float* gateW = (const float*)d_in[5];
    float* out = (float*)d_out;

    __half *w1h, *w2h, *cq, *xh, *x0h, *zh, *hh;
    float *gbuf;
    cudaGetSymbolAddress((void**)&w1h,  g_W1h);
    cudaGetSymbolAddress((void**)&w2h,  g_W2h);
    cudaGetSymbolAddress((void**)&cq,   g_Cq);
    cudaGetSymbolAddress((void**)&xh,   g_Xh);
    cudaGetSymbolAddress((void**)&x0h,  g_X0h);
    cudaGetSymbolAddress((void**)&zh,   g_Zh);
    cudaGetSymbolAddress((void**)&hh,   g_Hh);
    cudaGetSymbolAddress((void**)&gbuf, g_Gate);

    const int GEMM_SMEM = 5 * 16384;
    const int Z_SMEM    = 24576;
    cudaFuncSetAttribute(mma_gemm<0, 1024>, cudaFuncAttributeMaxDynamicSharedMemorySize, GEMM_SMEM);
    cudaFuncSetAttribute(mma_gemm<1, 256>,  cudaFuncAttributeMaxDynamicSharedMemorySize, GEMM_SMEM);
    cudaFuncSetAttribute(mma_gemm<2, 256>,  cudaFuncAttributeMaxDynamicSharedMemorySize, GEMM_SMEM);
    cudaFuncSetAttribute(zgemm_bd,          cudaFuncAttributeMaxDynamicSharedMemorySize, Z_SMEM);

    repack_w1_kernel<<<L_NUM * E_NUM * (D_DIM / 64), 256>>>(V);
    repack_w2_kernel<<<(L_NUM * D_DIM * N1 + 255) / 256, 256>>>(U);
    repack_c_kernel<<<(L_NUM * E_NUM * R_DIM * R_DIM + 255) / 256, 256>>>(C);
    convert_x_kernel<<<B_ROWS * D_DIM / 4 / 256, 256>>>(x);

    for (int i = 0; i < L_NUM; i++) {
        const size_t woff = (size_t)i * N1 * D_DIM;
        const __half* xin = (i == 0) ? x0h : xh;

        // GEMM1: Hh = fp16(tanh(Xin @ W1^T))   [16384 x 256], K = 1024
        mma_gemm<0, 1024><<<dim3(2, B_ROWS / 128), 256, GEMM_SMEM>>>(
            xin, w1h + woff, nullptr, nullptr, nullptr, nullptr, hh, N1);

        // gate logits + softmax
        gate_kernel<<<B_ROWS / 16, 256>>>(xin, gateW, gbuf);

        // Block-diagonal ZGEMM (K=64 per expert)
        zgemm_bd<<<dim3(E_NUM, B_ROWS / 128), 256, Z_SMEM>>>(
            hh, cq + (size_t)i * E_NUM * R_DIM * R_DIM, gbuf, zh);

        // GEMM2  [16384 x 1024], K = 256
        if (i == 0) {
            mma_gemm<2, 256><<<dim3(8, B_ROWS / 128), 256, GEMM_SMEM>>>(
                zh, w2h + woff, x0h, nullptr, bias, nullptr, xh, D_DIM);
        } else {
            mma_gemm<1, 256><<<dim3(8, B_ROWS / 128), 256, GEMM_SMEM>>>(
                zh, w2h + woff, x0h, xh, bias + (size_t)i * D_DIM, out, nullptr, D_DIM);
        }
    }
}

// round 13
// speedup vs baseline: 1.3702x; 1.0221x over previous
#include <cuda_runtime.h>
#include <cuda_fp16.h>
#include <math.h>
#include <stdint.h>

#define B_ROWS 16384
#define D_DIM  1024
#define R_DIM  64
#define E_NUM  4
#define L_NUM  2
#define N1     256   // E * R

// ---------------------------------------------------------------------------
// Device scratch (all intermediates fp16)
// ---------------------------------------------------------------------------
__device__ __half g_W1h[L_NUM * N1 * D_DIM];   // [L][n=e*64+r][k=d]  fp16(V)
__device__ __half g_W2h[L_NUM * D_DIM * N1];   // [L][n=d][k=e*64+r]  fp16(U)
__device__ __half g_Cq [L_NUM * E_NUM * R_DIM * R_DIM];  // fp16(C), native layout
__device__ __half g_Xh [B_ROWS * D_DIM];       // fp16(x_l) after layer 0
__device__ __half g_X0h[B_ROWS * D_DIM];       // fp16(x0)
__device__ __half g_Zh [B_ROWS * N1];          // fp16(Z)
__device__ float g_Gate[B_ROWS * E_NUM];

// ---------------------------------------------------------------------------
// Helpers
// ---------------------------------------------------------------------------
__device__ __forceinline__ uint32_t smem_u32(const void* p) {
    uint32_t a;
    asm("{ .reg .u64 t; cvta.to.shared.u64 t, %1; cvt.u32.u64 %0, t; }"
        : "=r"(a) : "l"(p));
    return a;
}

#define CP_ASYNC16(dst, src) \
    asm volatile("cp.async.cg.shared.global [%0], [%1], 16;" :: "r"(dst), "l"(src))
#define CP_COMMIT() asm volatile("cp.async.commit_group;" ::: "memory")

template<int N>
__device__ __forceinline__ void cp_wait() {
    asm volatile("cp.async.wait_group %0;" :: "n"(N) : "memory");
}

#define LDSM_X4(r0, r1, r2, r3, addr) \
    asm volatile("ldmatrix.sync.aligned.m8n8.x4.shared.b16 {%0,%1,%2,%3}, [%4];" \
        : "=r"(r0), "=r"(r1), "=r"(r2), "=r"(r3) : "r"(addr))

#define MMA_F16(d, a, b0, b1) \
    asm volatile("mma.sync.aligned.m16n8k16.row.col.f32.f16.f16.f32 " \
        "{%0,%1,%2,%3}, {%4,%5,%6,%7}, {%8,%9}, {%0,%1,%2,%3};" \
        : "+f"((d)[0]), "+f"((d)[1]), "+f"((d)[2]), "+f"((d)[3]) \
        : "r"((a)[0]), "r"((a)[1]), "r"((a)[2]), "r"((a)[3]), "r"(b0), "r"(b1))

// ---------------------------------------------------------------------------
// Weight repacks (fp16)
// ---------------------------------------------------------------------------
__global__ void repack_w1_kernel(const float* __restrict__ V) {
    __shared__ float tile[64][65];
    const int blk  = blockIdx.x;
    const int dblk = blk & 15;          // D/64 = 16
    const int e    = (blk >> 4) & 3;
    const int i    = blk >> 6;
    const int tid  = threadIdx.x;

    const float* src = V + (((size_t)i * E_NUM + e) * D_DIM + dblk * 64) * R_DIM;
    #pragma unroll
    for (int it = 0; it < 16; it++) {
        int lin = tid + it * 256;
        int dr = lin >> 6, rr = lin & 63;
        tile[dr][rr] = src[dr * 64 + rr];
    }
    __syncthreads();
    __half* dst = g_W1h + ((size_t)i * N1 + e * 64) * D_DIM + dblk * 64;
    #pragma unroll
    for (int it = 0; it < 16; it++) {
        int lin = tid + it * 256;
        int rr = lin >> 6, dr = lin & 63;
        dst[(size_t)rr * D_DIM + dr] = __float2half_rn(tile[dr][rr]);
    }
}

__global__ void repack_w2_kernel(const float* __restrict__ U) {
    int idx = blockIdx.x * blockDim.x + threadIdx.x;
    if (idx >= L_NUM * D_DIM * N1) return;
    int i   = idx / (D_DIM * N1);
    int rem = idx - i * (D_DIM * N1);
    int d = rem >> 8, k2 = rem & 255;
    int e = k2 >> 6, r = k2 & 63;
    g_W2h[idx] = __float2half_rn(U[(((size_t)i * E_NUM + e) * D_DIM + d) * R_DIM + r]);
}

__global__ void repack_c_kernel(const float* __restrict__ C) {
    int idx = blockIdx.x * blockDim.x + threadIdx.x;
    if (idx < L_NUM * E_NUM * R_DIM * R_DIM)
        g_Cq[idx] = __float2half_rn(C[idx]);
}

// ---------------------------------------------------------------------------
// Gate (layer 0): reads fp32 x, writes gate AND fp16 copy of x (x0h).
// 16 rows/block, warp handles 2 rows.
// ---------------------------------------------------------------------------
__global__ void __launch_bounds__(256)
gate_f32(const float* __restrict__ X, const float* __restrict__ gateW,
         float* __restrict__ gate, __half* __restrict__ X0h)
{
    __shared__ float sG[E_NUM * D_DIM];
    const int tid = threadIdx.x;
    #pragma unroll
    for (int i = tid * 4; i < E_NUM * D_DIM; i += 1024)
        *(float4*)(sG + i) = *(const float4*)(gateW + i);
    __syncthreads();

    const int warp = tid >> 5, lane = tid & 31;
    const int b = blockIdx.x * 16 + warp * 2;

    #pragma unroll
    for (int r = 0; r < 2; r++) {
        const float* xr = X + (size_t)(b + r) * D_DIM;
        __half* xo = X0h + (size_t)(b + r) * D_DIM;
        float a0 = 0.f, a1 = 0.f, a2 = 0.f, a3 = 0.f;
        #pragma unroll
        for (int j = 0; j < 4; j++) {
            const int off = lane * 8 + j * 256;
            float4 v0 = *(const float4*)(xr + off);
            float4 v1 = *(const float4*)(xr + off + 4);
            // fp16 copy
            __half2 p0, p1, p2, p3;
            p0.x = __float2half_rn(v0.x); p0.y = __float2half_rn(v0.y);
            p1.x = __float2half_rn(v0.z); p1.y = __float2half_rn(v0.w);
            p2.x = __float2half_rn(v1.x); p2.y = __float2half_rn(v1.y);
            p3.x = __float2half_rn(v1.z); p3.y = __float2half_rn(v1.w);
            uint4 pk;
            pk.x = *(uint32_t*)&p0; pk.y = *(uint32_t*)&p1;
            pk.z = *(uint32_t*)&p2; pk.w = *(uint32_t*)&p3;
            *(uint4*)(xo + off) = pk;
            #pragma unroll
            for (int e = 0; e < 4; e++) {
                float4 ga = *(const float4*)(sG + e * D_DIM + off);
                float4 gb = *(const float4*)(sG + e * D_DIM + off + 4);
                float p = v0.x * ga.x + v0.y * ga.y + v0.z * ga.z + v0.w * ga.w
                        + v1.x * gb.x + v1.y * gb.y + v1.z * gb.z + v1.w * gb.w;
                if (e == 0) a0 += p; else if (e == 1) a1 += p;
                else if (e == 2) a2 += p; else a3 += p;
            }
        }
        #pragma unroll
        for (int o = 16; o > 0; o >>= 1) {
            a0 += __shfl_xor_sync(0xffffffffu, a0, o);
            a1 += __shfl_xor_sync(0xffffffffu, a1, o);
            a2 += __shfl_xor_sync(0xffffffffu, a2, o);
            a3 += __shfl_xor_sync(0xffffffffu, a3, o);
        }
        if (lane == 0) {
            float mx = fmaxf(fmaxf(a0, a1), fmaxf(a2, a3));
            float e0 = expf(a0 - mx), e1 = expf(a1 - mx);
            float e2 = expf(a2 - mx), e3 = expf(a3 - mx);
            float inv = 1.0f / (e0 + e1 + e2 + e3);
            *(float4*)(gate + (size_t)(b + r) * 4) =
                make_float4(e0 * inv, e1 * inv, e2 * inv, e3 * inv);
        }
    }
}

// ---------------------------------------------------------------------------
// Gate (layer 1): reads fp16 x_l. 16 rows/block, warp handles 2 rows.
// ---------------------------------------------------------------------------
__global__ void __launch_bounds__(256)
gate_f16(const __half* __restrict__ Xh, const float* __restrict__ gateW,
         float* __restrict__ gate)
{
    __shared__ float sG[E_NUM * D_DIM];
    const int tid = threadIdx.x;
    #pragma unroll
    for (int i = tid * 4; i < E_NUM * D_DIM; i += 1024)
        *(float4*)(sG + i) = *(const float4*)(gateW + i);
    __syncthreads();

    const int warp = tid >> 5, lane = tid & 31;
    const int b = blockIdx.x * 16 + warp * 2;
    const __half* xr0 = Xh + (size_t)b * D_DIM;
    const __half* xr1 = xr0 + D_DIM;

    uint4 xv[2][4];
    #pragma unroll
    for (int j = 0; j < 4; j++) {
        const int off = lane * 8 + j * 256;
        xv[0][j] = *(const uint4*)(xr0 + off);
        xv[1][j] = *(const uint4*)(xr1 + off);
    }

    float acc[2][4];
    #pragma unroll
    for (int r = 0; r < 2; r++)
        #pragma unroll
        for (int e = 0; e < 4; e++) acc[r][e] = 0.0f;

    #pragma unroll
    for (int j = 0; j < 4; j++) {
        const int off = lane * 8 + j * 256;
        float2 xf[2][4];
        #pragma unroll
        for (int r = 0; r < 2; r++) {
            xf[r][0] = __half22float2(*(__half2*)&xv[r][j].x);
            xf[r][1] = __half22float2(*(__half2*)&xv[r][j].y);
            xf[r][2] = __half22float2(*(__half2*)&xv[r][j].z);
            xf[r][3] = __half22float2(*(__half2*)&xv[r][j].w);
        }
        #pragma unroll
        for (int e = 0; e < 4; e++) {
            float4 ga = *(const float4*)(sG + e * D_DIM + off);
            float4 gb = *(const float4*)(sG + e * D_DIM + off + 4);
            #pragma unroll
            for (int r = 0; r < 2; r++) {
                acc[r][e] += xf[r][0].x * ga.x + xf[r][0].y * ga.y
                           + xf[r][1].x * ga.z + xf[r][1].y * ga.w
                           + xf[r][2].x * gb.x + xf[r][2].y * gb.y
                           + xf[r][3].x * gb.z + xf[r][3].y * gb.w;
            }
        }
    }
    #pragma unroll
    for (int r = 0; r < 2; r++)
        #pragma unroll
        for (int e = 0; e < 4; e++)
            #pragma unroll
            for (int o = 16; o > 0; o >>= 1)
                acc[r][e] += __shfl_xor_sync(0xffffffffu, acc[r][e], o);

    if (lane < 2) {
        const int r = lane;
        float a0 = acc[r][0], a1 = acc[r][1], a2 = acc[r][2], a3 = acc[r][3];
        float mx = fmaxf(fmaxf(a0, a1), fmaxf(a2, a3));
        float e0 = expf(a0 - mx), e1 = expf(a1 - mx);
        float e2 = expf(a2 - mx), e3 = expf(a3 - mx);
        float inv = 1.0f / (e0 + e1 + e2 + e3);
        *(float4*)(gate + (size_t)(b + r) * 4) =
            make_float4(e0 * inv, e1 * inv, e2 * inv, e3 * inv);
    }
}

// ---------------------------------------------------------------------------
// Stage loader: 2 arrays (A, B), each 128 rows x 32 k (fp16) = 8KB.
// ---------------------------------------------------------------------------
template<int KDIM>
__device__ __forceinline__ void load_stage(
    uint32_t sbase,
    const __half* __restrict__ A, const __half* __restrict__ B,
    int k0, int tid)
{
    #pragma unroll
    for (int h = 0; h < 2; h++) {
        int c   = tid + h * 256;       // 0..511
        int row = c >> 2;
        int kb  = c & 3;
        size_t   go = (size_t)row * KDIM + k0 + kb * 8;
        uint32_t so = (uint32_t)(kb * 2048 + row * 16);
        CP_ASYNC16(sbase +         so, A + go);
        CP_ASYNC16(sbase + 8192u + so, B + go);
    }
}

// ---------------------------------------------------------------------------
// fp16 mma GEMM: BM=128, BN=128, BK=32, 8 warps (4m x 2n).
// MODE 0 (NST=3): GEMM1 fused — tanh(H) -> smem -> per-expert K=64 mma vs C
//                 -> Zh = fp16(gate * tanh(.)). C staged via cp.async.
// MODE 1 (NST=5): out  = xlh + x0h*(A@B + bias)   (fp32 final output)
// MODE 2 (NST=5): outh = fp16(x0h*(1 + A@B + bias))
// ---------------------------------------------------------------------------
template<int MODE, int KDIM, int NST>
__global__ void __launch_bounds__(256, 2)
mma_gemm(const __half* __restrict__ Ag, const __half* __restrict__ Bg,
         const __half* __restrict__ x0h, const __half* __restrict__ xlh,
         const float* __restrict__ bias, const float* __restrict__ gate,
         const __half* __restrict__ cq,
         float* __restrict__ out, __half* __restrict__ outh, int Nstride)
{
    constexpr int BK = 32, NK = KDIM / BK;
    constexpr uint32_t STAGE = 16384u;
    constexpr uint32_t CQ_OFF = (uint32_t)NST * STAGE;
    extern __shared__ char smem[];
    const uint32_t sbase = smem_u32(smem);

    const int tid  = threadIdx.x;
    const int wid  = tid >> 5;
    const int lane = tid & 31;
    const int wm   = wid & 3;
    const int wn   = wid >> 2;

    const __half* A = Ag + (size_t)blockIdx.y * 128 * KDIM;
    const __half* B = Bg + (size_t)blockIdx.x * 128 * KDIM;

    float acc[2][8][4];
    #pragma unroll
    for (int a = 0; a < 2; a++)
        #pragma unroll
        for (int b = 0; b < 8; b++)
            #pragma unroll
            for (int c = 0; c < 4; c++) acc[a][b][c] = 0.0f;

    if (MODE == 0) {
        // stage C for this CTA's 2 experts: [e][kb 0..7][row 0..63] panels
        #pragma unroll
        for (int h = 0; h < 4; h++) {
            int lin = tid + h * 256;          // 0..1023 chunks of 16B
            int e_l = lin >> 9;
            int rem = lin & 511;
            int row = rem >> 3, kb = rem & 7;
            const __half* src = cq + ((size_t)(blockIdx.x * 2 + e_l) * 64 + row) * 64 + kb * 8;
            CP_ASYNC16(sbase + CQ_OFF + (uint32_t)(e_l * 8192 + kb * 1024 + row * 16), src);
        }
        CP_COMMIT();
    }

    #pragma unroll
    for (int p = 0; p < NST - 1 && p < NK; p++) {
        load_stage<KDIM>(sbase + (uint32_t)p * STAGE, A, B, p * BK, tid);
        CP_COMMIT();
    }

    const uint32_t arow16 = (uint32_t)((wm * 32 + (lane & 15)) * 16);
    const uint32_t asel   = (uint32_t)(lane >> 4) * 2048u;
    const uint32_t brow16 = (uint32_t)((wn * 64 + (lane & 7) + ((lane >> 4) << 3)) * 16);
    const uint32_t bsel   = (uint32_t)((lane >> 3) & 1) * 2048u;

    for (int i = 0; i < NK; i++) {
        cp_wait<NST - 2>();
        __syncthreads();
        if (i + NST - 1 < NK) {
            load_stage<KDIM>(sbase + (uint32_t)((i + NST - 1) % NST) * STAGE,
                             A, B, (i + NST - 1) * BK, tid);
        }
        CP_COMMIT();

        const uint32_t st = sbase + (uint32_t)(i % NST) * STAGE;
        #pragma unroll
        for (int kk = 0; kk < 2; kk++) {
            const uint32_t kboff = (uint32_t)kk * 4096u;
            uint32_t ah[2][4], bb[4][4];

            #pragma unroll
            for (int g = 0; g < 4; g++) {
                uint32_t bd = st + 8192u + kboff + bsel + brow16 + (uint32_t)g * 256u;
                LDSM_X4(bb[g][0], bb[g][1], bb[g][2], bb[g][3], bd);
            }
            #pragma unroll
            for (int mt = 0; mt < 2; mt++) {
                uint32_t ad = st + kboff + asel + arow16 + (uint32_t)mt * 256u;
                LDSM_X4(ah[mt][0], ah[mt][1], ah[mt][2], ah[mt][3], ad);
            }
            #pragma unroll
            for (int mt = 0; mt < 2; mt++)
                #pragma unroll
                for (int nt = 0; nt < 8; nt++) {
                    const int g = nt >> 1, hh = (nt & 1) * 2;
                    MMA_F16(acc[mt][nt], ah[mt], bb[g][hh], bb[g][hh + 1]);
                }
        }
    }

    const int r0    = lane >> 2;
    const int cpair = (lane & 3) * 2;

    if (MODE == 0) {
        // ---- fused Z epilogue ----
        cp_wait<0>();
        __syncthreads();   // all mainloop smem reads done
        // tanh(H) tile -> smem panels: [e_l][kb=q>>3][row][16B]
        #pragma unroll
        for (int mt = 0; mt < 2; mt++)
            #pragma unroll
            for (int nt = 0; nt < 8; nt++) {
                const int col_l = wn * 64 + nt * 8 + cpair;
                const int e_l = col_l >> 6;          // == wn
                const int q   = col_l & 63;
                #pragma unroll
                for (int h = 0; h < 2; h++) {
                    const int row_l = wm * 32 + mt * 16 + r0 + h * 8;
                    __half2 hv;
                    hv.x = __float2half_rn(tanhf(acc[mt][nt][h * 2 + 0]));
                    hv.y = __float2half_rn(tanhf(acc[mt][nt][h * 2 + 1]));
                    *(__half2*)(smem + e_l * 16384 + (q >> 3) * 2048
                                + row_l * 16 + (q & 7) * 2) = hv;
                }
            }
        __syncthreads();

        // Z = tanhH @ C^T per expert; warp: expert wn, rows wm*32..+32, cols 0..63
        float zacc[2][8][4];
        #pragma unroll
        for (int a = 0; a < 2; a++)
            #pragma unroll
            for (int b = 0; b < 8; b++)
                #pragma unroll
                for (int c = 0; c < 4; c++) zacc[a][b][c] = 0.0f;

        const uint32_t HB = sbase + (uint32_t)wn * 16384u;
        const uint32_t CB = sbase + CQ_OFF + (uint32_t)wn * 8192u;
        const uint32_t zbrow16 = (uint32_t)(((lane & 7) + ((lane >> 4) << 3)) * 16);
        const uint32_t zbsel   = (uint32_t)((lane >> 3) & 1) * 1024u;

        #pragma unroll
        for (int kk = 0; kk < 4; kk++) {
            uint32_t ah[2][4], bb[4][4];
            #pragma unroll
            for (int g = 0; g < 4; g++) {
                uint32_t bd = CB + (uint32_t)(kk * 2048) + zbsel + zbrow16 + (uint32_t)g * 256u;
                LDSM_X4(bb[g][0], bb[g][1], bb[g][2], bb[g][3], bd);
            }
            #pragma unroll
            for (int mt = 0; mt < 2; mt++) {
                uint32_t ad = HB + (uint32_t)(kk * 4096) + asel + arow16 + (uint32_t)mt * 256u;
                LDSM_X4(ah[mt][0], ah[mt][1], ah[mt][2], ah[mt][3], ad);
            }
            #pragma unroll
            for (int mt = 0; mt < 2; mt++)
                #pragma unroll
                for (int nt = 0; nt < 8; nt++) {
                    const int g = nt >> 1, hh = (nt & 1) * 2;
                    MMA_F16(zacc[mt][nt], ah[mt], bb[g][hh], bb[g][hh + 1]);
                }
        }

        const int eg = blockIdx.x * 2 + wn;
        #pragma unroll
        for (int mt = 0; mt < 2; mt++)
            #pragma unroll
            for (int nt = 0; nt < 8; nt++) {
                const int row = blockIdx.y * 128 + wm * 32 + mt * 16 + r0;
                const int col = eg * 64 + nt * 8 + cpair;
                #pragma unroll
                for (int h = 0; h < 2; h++) {
                    const int rr = row + h * 8;
                    const float g = gate[(size_t)rr * 4 + eg];
                    __half2 hv;
                    hv.x = __float2half_rn(g * tanhf(zacc[mt][nt][h * 2 + 0]));
                    hv.y = __float2half_rn(g * tanhf(zacc[mt][nt][h * 2 + 1]));
                    *(__half2*)(outh + (size_t)rr * N1 + col) = hv;
                }
            }
    } else {
        #pragma unroll
        for (int mt = 0; mt < 2; mt++)
            #pragma unroll
            for (int nt = 0; nt < 8; nt++) {
                const int row = blockIdx.y * 128 + wm * 32 + mt * 16 + r0;
                const int col = blockIdx.x * 128 + wn * 64 + nt * 8 + cpair;
                #pragma unroll
                for (int h = 0; h < 2; h++) {
                    const int rr = row + h * 8;
                    const float v0 = acc[mt][nt][h * 2 + 0];
                    const float v1 = acc[mt][nt][h * 2 + 1];
                    const size_t o = (size_t)rr * Nstride + col;
                    if (MODE == 1) {
                        const float2 bv = *(const float2*)(bias + col);
                        const float2 xf = __half22float2(*(const __half2*)(x0h + o));
                        const float2 lf = __half22float2(*(const __half2*)(xlh + o));
                        float2 ov;
                        ov.x = fmaf(xf.x, v0 + bv.x, lf.x);
                        ov.y = fmaf(xf.y, v1 + bv.y, lf.y);
                        *(float2*)(out + o) = ov;
                    } else {
                        const float2 bv = *(const float2*)(bias + col);
                        const float2 xf = __half22float2(*(const __half2*)(x0h + o));
                        __half2 hv;
                        hv.x = __float2half_rn(xf.x * (1.0f + v0 + bv.x));
                        hv.y = __float2half_rn(xf.y * (1.0f + v1 + bv.y));
                        *(__half2*)(outh + o) = hv;
                    }
                }
            }
    }
}

// ---------------------------------------------------------------------------
extern "C" void kernel_launch(void* const* d_in, const int* in_sizes, int n_in,
                              void* d_out, int out_size)
{
    const float* x     = (const float*)d_in[0];
    const float* U     = (const float*)d_in[1];
    const float* V     = (const float*)d_in[2];
    const float* C     = (const float*)d_in[3];
    const float* bias  = (const float*)d_in[4];
    const float* gateW = (const float*)d_in[5];
    float* out = (float*)d_out;

    __half *w1h, *w2h, *cq, *xh, *x0h, *zh;
    float *gbuf;
    cudaGetSymbolAddress((void**)&w1h,  g_W1h);
    cudaGetSymbolAddress((void**)&w2h,  g_W2h);
    cudaGetSymbolAddress((void**)&cq,   g_Cq);
    cudaGetSymbolAddress((void**)&xh,   g_Xh);
    cudaGetSymbolAddress((void**)&x0h,  g_X0h);
    cudaGetSymbolAddress((void**)&zh,   g_Zh);
    cudaGetSymbolAddress((void**)&gbuf, g_Gate);

    const int G1_SMEM = 3 * 16384 + 16384;   // 64 KB (3 stages + C)
    const int G2_SMEM = 5 * 16384;           // 80 KB
    cudaFuncSetAttribute((const void*)mma_gemm<0, 1024, 3>,
                         cudaFuncAttributeMaxDynamicSharedMemorySize, G1_SMEM);
    cudaFuncSetAttribute((const void*)mma_gemm<1, 256, 5>,
                         cudaFuncAttributeMaxDynamicSharedMemorySize, G2_SMEM);
    cudaFuncSetAttribute((const void*)mma_gemm<2, 256, 5>,
                         cudaFuncAttributeMaxDynamicSharedMemorySize, G2_SMEM);

    repack_w1_kernel<<<L_NUM * E_NUM * (D_DIM / 64), 256>>>(V);
    repack_w2_kernel<<<(L_NUM * D_DIM * N1 + 255) / 256, 256>>>(U);
    repack_c_kernel<<<(L_NUM * E_NUM * R_DIM * R_DIM + 255) / 256, 256>>>(C);

    for (int i = 0; i < L_NUM; i++) {
        const size_t woff = (size_t)i * N1 * D_DIM;
        const __half* cql = cq + (size_t)i * E_NUM * R_DIM * R_DIM;
        const __half* xin = (i == 0) ? x0h : xh;

        // gate (layer 0 also emits x0h)
        if (i == 0)
            gate_f32<<<B_ROWS / 16, 256>>>(x, gateW, gbuf, x0h);
        else
            gate_f16<<<B_ROWS / 16, 256>>>(xh, gateW, gbuf);

        // GEMM1 fused: Zh = fp16(gate * tanh(C @ tanh(Xin @ W1^T)))
        mma_gemm<0, 1024, 3><<<dim3(2, B_ROWS / 128), 256, G1_SMEM>>>(
            xin, w1h + woff, nullptr, nullptr, nullptr, gbuf, cql,
            nullptr, zh, N1);

        // GEMM2  [16384 x 1024], K = 256
        if (i == 0) {
            mma_gemm<2, 256, 5><<<dim3(8, B_ROWS / 128), 256, G2_SMEM>>>(
                zh, w2h + woff, x0h, nullptr, bias, nullptr, nullptr,
                nullptr, xh, D_DIM);
        } else {
            mma_gemm<1, 256, 5><<<dim3(8, B_ROWS / 128), 256, G2_SMEM>>>(
                zh, w2h + woff, x0h, xh, bias + (size_t)i * D_DIM, nullptr, nullptr,
                out, nullptr, D_DIM);
        }
    }
}

// round 14
// speedup vs baseline: 1.4390x; 1.0502x over previous
#include <cuda_runtime.h>
#include <cuda_fp16.h>
#include <math.h>
#include <stdint.h>

#define B_ROWS 16384
#define D_DIM  1024
#define R_DIM  64
#define E_NUM  4
#define L_NUM  2
#define N1     256   // E * R

// ---------------------------------------------------------------------------
// Device scratch (all intermediates fp16)
// ---------------------------------------------------------------------------
__device__ __half g_W1h[L_NUM * N1 * D_DIM];   // [L][n=e*64+r][k=d]  fp16(V)
__device__ __half g_W2h[L_NUM * D_DIM * N1];   // [L][n=d][k=e*64+r]  fp16(U)
__device__ __half g_Cq [L_NUM * E_NUM * R_DIM * R_DIM];  // fp16(C), native layout
__device__ __half g_Xh [B_ROWS * D_DIM];       // fp16(x_l) after layer 0
__device__ __half g_X0h[B_ROWS * D_DIM];       // fp16(x0)
__device__ __half g_Zh [B_ROWS * N1];          // fp16(Z)
__device__ float g_Gate[B_ROWS * E_NUM];

// ---------------------------------------------------------------------------
// Helpers
// ---------------------------------------------------------------------------
__device__ __forceinline__ uint32_t smem_u32(const void* p) {
    uint32_t a;
    asm("{ .reg .u64 t; cvta.to.shared.u64 t, %1; cvt.u32.u64 %0, t; }"
        : "=r"(a) : "l"(p));
    return a;
}

#define CP_ASYNC16(dst, src) \
    asm volatile("cp.async.cg.shared.global [%0], [%1], 16;" :: "r"(dst), "l"(src))
#define CP_COMMIT() asm volatile("cp.async.commit_group;" ::: "memory")

template<int N>
__device__ __forceinline__ void cp_wait() {
    asm volatile("cp.async.wait_group %0;" :: "n"(N) : "memory");
}

#define LDSM_X4(r0, r1, r2, r3, addr) \
    asm volatile("ldmatrix.sync.aligned.m8n8.x4.shared.b16 {%0,%1,%2,%3}, [%4];" \
        : "=r"(r0), "=r"(r1), "=r"(r2), "=r"(r3) : "r"(addr))

#define MMA_F16(d, a, b0, b1) \
    asm volatile("mma.sync.aligned.m16n8k16.row.col.f32.f16.f16.f32 " \
        "{%0,%1,%2,%3}, {%4,%5,%6,%7}, {%8,%9}, {%0,%1,%2,%3};" \
        : "+f"((d)[0]), "+f"((d)[1]), "+f"((d)[2]), "+f"((d)[3]) \
        : "r"((a)[0]), "r"((a)[1]), "r"((a)[2]), "r"((a)[3]), "r"(b0), "r"(b1))

// ---------------------------------------------------------------------------
// Weight repacks (fp16)
// ---------------------------------------------------------------------------
__global__ void repack_w1_kernel(const float* __restrict__ V) {
    __shared__ float tile[64][65];
    const int blk  = blockIdx.x;
    const int dblk = blk & 15;          // D/64 = 16
    const int e    = (blk >> 4) & 3;
    const int i    = blk >> 6;
    const int tid  = threadIdx.x;

    const float* src = V + (((size_t)i * E_NUM + e) * D_DIM + dblk * 64) * R_DIM;
    #pragma unroll
    for (int it = 0; it < 16; it++) {
        int lin = tid + it * 256;
        int dr = lin >> 6, rr = lin & 63;
        tile[dr][rr] = src[dr * 64 + rr];
    }
    __syncthreads();
    __half* dst = g_W1h + ((size_t)i * N1 + e * 64) * D_DIM + dblk * 64;
    #pragma unroll
    for (int it = 0; it < 16; it++) {
        int lin = tid + it * 256;
        int rr = lin >> 6, dr = lin & 63;
        dst[(size_t)rr * D_DIM + dr] = __float2half_rn(tile[dr][rr]);
    }
}

__global__ void repack_w2_kernel(const float* __restrict__ U) {
    int idx = blockIdx.x * blockDim.x + threadIdx.x;
    if (idx >= L_NUM * D_DIM * N1) return;
    int i   = idx / (D_DIM * N1);
    int rem = idx - i * (D_DIM * N1);
    int d = rem >> 8, k2 = rem & 255;
    int e = k2 >> 6, r = k2 & 63;
    g_W2h[idx] = __float2half_rn(U[(((size_t)i * E_NUM + e) * D_DIM + d) * R_DIM + r]);
}

__global__ void repack_c_kernel(const float* __restrict__ C) {
    int idx = blockIdx.x * blockDim.x + threadIdx.x;
    if (idx < L_NUM * E_NUM * R_DIM * R_DIM)
        g_Cq[idx] = __float2half_rn(C[idx]);
}

// ---------------------------------------------------------------------------
// Gate (layer 0): one row per warp; reads fp32 x, writes gate + fp16 x copy.
// Minimal live set per j-chunk to keep regs low / occupancy high.
// ---------------------------------------------------------------------------
__global__ void __launch_bounds__(256)
gate_f32(const float* __restrict__ X, const float* __restrict__ gateW,
         float* __restrict__ gate, __half* __restrict__ X0h)
{
    __shared__ float sG[E_NUM * D_DIM];
    const int tid = threadIdx.x;
    #pragma unroll
    for (int i = tid * 4; i < E_NUM * D_DIM; i += 1024)
        *(float4*)(sG + i) = *(const float4*)(gateW + i);
    __syncthreads();

    const int warp = tid >> 5, lane = tid & 31;
    const int b = blockIdx.x * 8 + warp;
    const float* xr = X + (size_t)b * D_DIM;
    __half* xo = X0h + (size_t)b * D_DIM;

    float a0 = 0.f, a1 = 0.f, a2 = 0.f, a3 = 0.f;
    #pragma unroll
    for (int j = 0; j < 8; j++) {
        const int off = lane * 4 + j * 128;
        float4 xv = *(const float4*)(xr + off);
        // fp16 copy (8 bytes)
        __half2 p0, p1;
        p0.x = __float2half_rn(xv.x); p0.y = __float2half_rn(xv.y);
        p1.x = __float2half_rn(xv.z); p1.y = __float2half_rn(xv.w);
        uint2 pk;
        pk.x = *(uint32_t*)&p0; pk.y = *(uint32_t*)&p1;
        *(uint2*)(xo + off) = pk;

        float4 g0 = *(const float4*)(sG + 0 * D_DIM + off);
        float4 g1 = *(const float4*)(sG + 1 * D_DIM + off);
        float4 g2 = *(const float4*)(sG + 2 * D_DIM + off);
        float4 g3 = *(const float4*)(sG + 3 * D_DIM + off);
        a0 += xv.x * g0.x + xv.y * g0.y + xv.z * g0.z + xv.w * g0.w;
        a1 += xv.x * g1.x + xv.y * g1.y + xv.z * g1.z + xv.w * g1.w;
        a2 += xv.x * g2.x + xv.y * g2.y + xv.z * g2.z + xv.w * g2.w;
        a3 += xv.x * g3.x + xv.y * g3.y + xv.z * g3.z + xv.w * g3.w;
    }
    #pragma unroll
    for (int o = 16; o > 0; o >>= 1) {
        a0 += __shfl_xor_sync(0xffffffffu, a0, o);
        a1 += __shfl_xor_sync(0xffffffffu, a1, o);
        a2 += __shfl_xor_sync(0xffffffffu, a2, o);
        a3 += __shfl_xor_sync(0xffffffffu, a3, o);
    }
    if (lane == 0) {
        float mx = fmaxf(fmaxf(a0, a1), fmaxf(a2, a3));
        float e0 = expf(a0 - mx), e1 = expf(a1 - mx);
        float e2 = expf(a2 - mx), e3 = expf(a3 - mx);
        float inv = 1.0f / (e0 + e1 + e2 + e3);
        *(float4*)(gate + (size_t)b * 4) =
            make_float4(e0 * inv, e1 * inv, e2 * inv, e3 * inv);
    }
}

// ---------------------------------------------------------------------------
// Gate (layer 1): reads fp16 x_l. 16 rows/block, warp handles 2 rows.
// ---------------------------------------------------------------------------
__global__ void __launch_bounds__(256)
gate_f16(const __half* __restrict__ Xh, const float* __restrict__ gateW,
         float* __restrict__ gate)
{
    __shared__ float sG[E_NUM * D_DIM];
    const int tid = threadIdx.x;
    #pragma unroll
    for (int i = tid * 4; i < E_NUM * D_DIM; i += 1024)
        *(float4*)(sG + i) = *(const float4*)(gateW + i);
    __syncthreads();

    const int warp = tid >> 5, lane = tid & 31;
    const int b = blockIdx.x * 16 + warp * 2;
    const __half* xr0 = Xh + (size_t)b * D_DIM;
    const __half* xr1 = xr0 + D_DIM;

    uint4 xv[2][4];
    #pragma unroll
    for (int j = 0; j < 4; j++) {
        const int off = lane * 8 + j * 256;
        xv[0][j] = *(const uint4*)(xr0 + off);
        xv[1][j] = *(const uint4*)(xr1 + off);
    }

    float acc[2][4];
    #pragma unroll
    for (int r = 0; r < 2; r++)
        #pragma unroll
        for (int e = 0; e < 4; e++) acc[r][e] = 0.0f;

    #pragma unroll
    for (int j = 0; j < 4; j++) {
        const int off = lane * 8 + j * 256;
        float2 xf[2][4];
        #pragma unroll
        for (int r = 0; r < 2; r++) {
            xf[r][0] = __half22float2(*(__half2*)&xv[r][j].x);
            xf[r][1] = __half22float2(*(__half2*)&xv[r][j].y);
            xf[r][2] = __half22float2(*(__half2*)&xv[r][j].z);
            xf[r][3] = __half22float2(*(__half2*)&xv[r][j].w);
        }
        #pragma unroll
        for (int e = 0; e < 4; e++) {
            float4 ga = *(const float4*)(sG + e * D_DIM + off);
            float4 gb = *(const float4*)(sG + e * D_DIM + off + 4);
            #pragma unroll
            for (int r = 0; r < 2; r++) {
                acc[r][e] += xf[r][0].x * ga.x + xf[r][0].y * ga.y
                           + xf[r][1].x * ga.z + xf[r][1].y * ga.w
                           + xf[r][2].x * gb.x + xf[r][2].y * gb.y
                           + xf[r][3].x * gb.z + xf[r][3].y * gb.w;
            }
        }
    }
    #pragma unroll
    for (int r = 0; r < 2; r++)
        #pragma unroll
        for (int e = 0; e < 4; e++)
            #pragma unroll
            for (int o = 16; o > 0; o >>= 1)
                acc[r][e] += __shfl_xor_sync(0xffffffffu, acc[r][e], o);

    if (lane < 2) {
        const int r = lane;
        float a0 = acc[r][0], a1 = acc[r][1], a2 = acc[r][2], a3 = acc[r][3];
        float mx = fmaxf(fmaxf(a0, a1), fmaxf(a2, a3));
        float e0 = expf(a0 - mx), e1 = expf(a1 - mx);
        float e2 = expf(a2 - mx), e3 = expf(a3 - mx);
        float inv = 1.0f / (e0 + e1 + e2 + e3);
        *(float4*)(gate + (size_t)(b + r) * 4) =
            make_float4(e0 * inv, e1 * inv, e2 * inv, e3 * inv);
    }
}

// ---------------------------------------------------------------------------
// Stage loader: 2 arrays (A, B), each 128 rows x 32 k (fp16) = 8KB.
// ---------------------------------------------------------------------------
template<int KDIM>
__device__ __forceinline__ void load_stage(
    uint32_t sbase,
    const __half* __restrict__ A, const __half* __restrict__ B,
    int k0, int tid)
{
    #pragma unroll
    for (int h = 0; h < 2; h++) {
        int c   = tid + h * 256;       // 0..511
        int row = c >> 2;
        int kb  = c & 3;
        size_t   go = (size_t)row * KDIM + k0 + kb * 8;
        uint32_t so = (uint32_t)(kb * 2048 + row * 16);
        CP_ASYNC16(sbase +         so, A + go);
        CP_ASYNC16(sbase + 8192u + so, B + go);
    }
}

// ---------------------------------------------------------------------------
// fp16 mma GEMM: BM=128, BN=128, BK=32, 8 warps (4m x 2n).
// MODE 0 (NST=3): GEMM1 fused — tanh(H) -> smem -> per-expert K=64 mma vs C
//                 -> Zh = fp16(gate * tanh(.)). C staged via cp.async.
// MODE 1 (NST=5): out  = xlh + x0h*(A@B + bias)   (fp32 final output)
// MODE 2 (NST=5): outh = fp16(x0h*(1 + A@B + bias))
// ---------------------------------------------------------------------------
template<int MODE, int KDIM, int NST>
__global__ void __launch_bounds__(256, 2)
mma_gemm(const __half* __restrict__ Ag, const __half* __restrict__ Bg,
         const __half* __restrict__ x0h, const __half* __restrict__ xlh,
         const float* __restrict__ bias, const float* __restrict__ gate,
         const __half* __restrict__ cq,
         float* __restrict__ out, __half* __restrict__ outh, int Nstride)
{
    constexpr int BK = 32, NK = KDIM / BK;
    constexpr uint32_t STAGE = 16384u;
    constexpr uint32_t CQ_OFF = (uint32_t)NST * STAGE;
    extern __shared__ char smem[];
    const uint32_t sbase = smem_u32(smem);

    const int tid  = threadIdx.x;
    const int wid  = tid >> 5;
    const int lane = tid & 31;
    const int wm   = wid & 3;
    const int wn   = wid >> 2;

    const __half* A = Ag + (size_t)blockIdx.y * 128 * KDIM;
    const __half* B = Bg + (size_t)blockIdx.x * 128 * KDIM;

    float acc[2][8][4];
    #pragma unroll
    for (int a = 0; a < 2; a++)
        #pragma unroll
        for (int b = 0; b < 8; b++)
            #pragma unroll
            for (int c = 0; c < 4; c++) acc[a][b][c] = 0.0f;

    if (MODE == 0) {
        // stage C for this CTA's 2 experts: [e][kb 0..7][row 0..63] panels
        #pragma unroll
        for (int h = 0; h < 4; h++) {
            int lin = tid + h * 256;          // 0..1023 chunks of 16B
            int e_l = lin >> 9;
            int rem = lin & 511;
            int row = rem >> 3, kb = rem & 7;
            const __half* src = cq + ((size_t)(blockIdx.x * 2 + e_l) * 64 + row) * 64 + kb * 8;
            CP_ASYNC16(sbase + CQ_OFF + (uint32_t)(e_l * 8192 + kb * 1024 + row * 16), src);
        }
        CP_COMMIT();
    }

    #pragma unroll
    for (int p = 0; p < NST - 1 && p < NK; p++) {
        load_stage<KDIM>(sbase + (uint32_t)p * STAGE, A, B, p * BK, tid);
        CP_COMMIT();
    }

    const uint32_t arow16 = (uint32_t)((wm * 32 + (lane & 15)) * 16);
    const uint32_t asel   = (uint32_t)(lane >> 4) * 2048u;
    const uint32_t brow16 = (uint32_t)((wn * 64 + (lane & 7) + ((lane >> 4) << 3)) * 16);
    const uint32_t bsel   = (uint32_t)((lane >> 3) & 1) * 2048u;

    for (int i = 0; i < NK; i++) {
        cp_wait<NST - 2>();
        __syncthreads();
        if (i + NST - 1 < NK) {
            load_stage<KDIM>(sbase + (uint32_t)((i + NST - 1) % NST) * STAGE,
                             A, B, (i + NST - 1) * BK, tid);
        }
        CP_COMMIT();

        const uint32_t st = sbase + (uint32_t)(i % NST) * STAGE;
        #pragma unroll
        for (int kk = 0; kk < 2; kk++) {
            const uint32_t kboff = (uint32_t)kk * 4096u;
            uint32_t ah[2][4], bb[4][4];

            #pragma unroll
            for (int g = 0; g < 4; g++) {
                uint32_t bd = st + 8192u + kboff + bsel + brow16 + (uint32_t)g * 256u;
                LDSM_X4(bb[g][0], bb[g][1], bb[g][2], bb[g][3], bd);
            }
            #pragma unroll
            for (int mt = 0; mt < 2; mt++) {
                uint32_t ad = st + kboff + asel + arow16 + (uint32_t)mt * 256u;
                LDSM_X4(ah[mt][0], ah[mt][1], ah[mt][2], ah[mt][3], ad);
            }
            #pragma unroll
            for (int mt = 0; mt < 2; mt++)
                #pragma unroll
                for (int nt = 0; nt < 8; nt++) {
                    const int g = nt >> 1, hh = (nt & 1) * 2;
                    MMA_F16(acc[mt][nt], ah[mt], bb[g][hh], bb[g][hh + 1]);
                }
        }
    }

    const int r0    = lane >> 2;
    const int cpair = (lane & 3) * 2;

    if (MODE == 0) {
        // ---- fused Z epilogue ----
        cp_wait<0>();
        __syncthreads();   // all mainloop smem reads done
        // tanh(H) tile -> smem panels: [e_l][kb=q>>3][row][16B]
        #pragma unroll
        for (int mt = 0; mt < 2; mt++)
            #pragma unroll
            for (int nt = 0; nt < 8; nt++) {
                const int col_l = wn * 64 + nt * 8 + cpair;
                const int e_l = col_l >> 6;          // == wn
                const int q   = col_l & 63;
                #pragma unroll
                for (int h = 0; h < 2; h++) {
                    const int row_l = wm * 32 + mt * 16 + r0 + h * 8;
                    __half2 hv;
                    hv.x = __float2half_rn(tanhf(acc[mt][nt][h * 2 + 0]));
                    hv.y = __float2half_rn(tanhf(acc[mt][nt][h * 2 + 1]));
                    *(__half2*)(smem + e_l * 16384 + (q >> 3) * 2048
                                + row_l * 16 + (q & 7) * 2) = hv;
                }
            }
        __syncthreads();

        // Z = tanhH @ C^T per expert; warp: expert wn, rows wm*32..+32, cols 0..63
        float zacc[2][8][4];
        #pragma unroll
        for (int a = 0; a < 2; a++)
            #pragma unroll
            for (int b = 0; b < 8; b++)
                #pragma unroll
                for (int c = 0; c < 4; c++) zacc[a][b][c] = 0.0f;

        const uint32_t HB = sbase + (uint32_t)wn * 16384u;
        const uint32_t CB = sbase + CQ_OFF + (uint32_t)wn * 8192u;
        const uint32_t zbrow16 = (uint32_t)(((lane & 7) + ((lane >> 4) << 3)) * 16);
        const uint32_t zbsel   = (uint32_t)((lane >> 3) & 1) * 1024u;

        #pragma unroll
        for (int kk = 0; kk < 4; kk++) {
            uint32_t ah[2][4], bb[4][4];
            #pragma unroll
            for (int g = 0; g < 4; g++) {
                uint32_t bd = CB + (uint32_t)(kk * 2048) + zbsel + zbrow16 + (uint32_t)g * 256u;
                LDSM_X4(bb[g][0], bb[g][1], bb[g][2], bb[g][3], bd);
            }
            #pragma unroll
            for (int mt = 0; mt < 2; mt++) {
                uint32_t ad = HB + (uint32_t)(kk * 4096) + asel + arow16 + (uint32_t)mt * 256u;
                LDSM_X4(ah[mt][0], ah[mt][1], ah[mt][2], ah[mt][3], ad);
            }
            #pragma unroll
            for (int mt = 0; mt < 2; mt++)
                #pragma unroll
                for (int nt = 0; nt < 8; nt++) {
                    const int g = nt >> 1, hh = (nt & 1) * 2;
                    MMA_F16(zacc[mt][nt], ah[mt], bb[g][hh], bb[g][hh + 1]);
                }
        }

        const int eg = blockIdx.x * 2 + wn;
        #pragma unroll
        for (int mt = 0; mt < 2; mt++)
            #pragma unroll
            for (int nt = 0; nt < 8; nt++) {
                const int row = blockIdx.y * 128 + wm * 32 + mt * 16 + r0;
                const int col = eg * 64 + nt * 8 + cpair;
                #pragma unroll
                for (int h = 0; h < 2; h++) {
                    const int rr = row + h * 8;
                    const float g = gate[(size_t)rr * 4 + eg];
                    __half2 hv;
                    hv.x = __float2half_rn(g * tanhf(zacc[mt][nt][h * 2 + 0]));
                    hv.y = __float2half_rn(g * tanhf(zacc[mt][nt][h * 2 + 1]));
                    *(__half2*)(outh + (size_t)rr * N1 + col) = hv;
                }
            }
    } else {
        #pragma unroll
        for (int mt = 0; mt < 2; mt++)
            #pragma unroll
            for (int nt = 0; nt < 8; nt++) {
                const int row = blockIdx.y * 128 + wm * 32 + mt * 16 + r0;
                const int col = blockIdx.x * 128 + wn * 64 + nt * 8 + cpair;
                #pragma unroll
                for (int h = 0; h < 2; h++) {
                    const int rr = row + h * 8;
                    const float v0 = acc[mt][nt][h * 2 + 0];
                    const float v1 = acc[mt][nt][h * 2 + 1];
                    const size_t o = (size_t)rr * Nstride + col;
                    if (MODE == 1) {
                        const float2 bv = *(const float2*)(bias + col);
                        const float2 xf = __half22float2(*(const __half2*)(x0h + o));
                        const float2 lf = __half22float2(*(const __half2*)(xlh + o));
                        float2 ov;
                        ov.x = fmaf(xf.x, v0 + bv.x, lf.x);
                        ov.y = fmaf(xf.y, v1 + bv.y, lf.y);
                        *(float2*)(out + o) = ov;
                    } else {
                        const float2 bv = *(const float2*)(bias + col);
                        const float2 xf = __half22float2(*(const __half2*)(x0h + o));
                        __half2 hv;
                        hv.x = __float2half_rn(xf.x * (1.0f + v0 + bv.x));
                        hv.y = __float2half_rn(xf.y * (1.0f + v1 + bv.y));
                        *(__half2*)(outh + o) = hv;
                    }
                }
            }
    }
}

// ---------------------------------------------------------------------------
extern "C" void kernel_launch(void* const* d_in, const int* in_sizes, int n_in,
                              void* d_out, int out_size)
{
    const float* x     = (const float*)d_in[0];
    const float* U     = (const float*)d_in[1];
    const float* V     = (const float*)d_in[2];
    const float* C     = (const float*)d_in[3];
    const float* bias  = (const float*)d_in[4];
    const float* gateW = (const float*)d_in[5];
    float* out = (float*)d_out;

    __half *w1h, *w2h, *cq, *xh, *x0h, *zh;
    float *gbuf;
    cudaGetSymbolAddress((void**)&w1h,  g_W1h);
    cudaGetSymbolAddress((void**)&w2h,  g_W2h);
    cudaGetSymbolAddress((void**)&cq,   g_Cq);
    cudaGetSymbolAddress((void**)&xh,   g_Xh);
    cudaGetSymbolAddress((void**)&x0h,  g_X0h);
    cudaGetSymbolAddress((void**)&zh,   g_Zh);
    cudaGetSymbolAddress((void**)&gbuf, g_Gate);

    const int G1_SMEM = 3 * 16384 + 16384;   // 64 KB (3 stages + C)
    const int G2_SMEM = 5 * 16384;           // 80 KB
    cudaFuncSetAttribute((const void*)mma_gemm<0, 1024, 3>,
                         cudaFuncAttributeMaxDynamicSharedMemorySize, G1_SMEM);
    cudaFuncSetAttribute((const void*)mma_gemm<1, 256, 5>,
                         cudaFuncAttributeMaxDynamicSharedMemorySize, G2_SMEM);
    cudaFuncSetAttribute((const void*)mma_gemm<2, 256, 5>,
                         cudaFuncAttributeMaxDynamicSharedMemorySize, G2_SMEM);

    repack_w1_kernel<<<L_NUM * E_NUM * (D_DIM / 64), 256>>>(V);
    repack_w2_kernel<<<(L_NUM * D_DIM * N1 + 255) / 256, 256>>>(U);
    repack_c_kernel<<<(L_NUM * E_NUM * R_DIM * R_DIM + 255) / 256, 256>>>(C);

    for (int i = 0; i < L_NUM; i++) {
        const size_t woff = (size_t)i * N1 * D_DIM;
        const __half* cql = cq + (size_t)i * E_NUM * R_DIM * R_DIM;
        const __half* xin = (i == 0) ? x0h : xh;

        // gate (layer 0 also emits x0h)
        if (i == 0)
            gate_f32<<<B_ROWS / 8, 256>>>(x, gateW, gbuf, x0h);
        else
            gate_f16<<<B_ROWS / 16, 256>>>(xh, gateW, gbuf);

        // GEMM1 fused: Zh = fp16(gate * tanh(C @ tanh(Xin @ W1^T)))
        mma_gemm<0, 1024, 3><<<dim3(2, B_ROWS / 128), 256, G1_SMEM>>>(
            xin, w1h + woff, nullptr, nullptr, nullptr, gbuf, cql,
            nullptr, zh, N1);

        // GEMM2  [16384 x 1024], K = 256
        if (i == 0) {
            mma_gemm<2, 256, 5><<<dim3(8, B_ROWS / 128), 256, G2_SMEM>>>(
                zh, w2h + woff, x0h, nullptr, bias, nullptr, nullptr,
                nullptr, xh, D_DIM);
        } else {
            mma_gemm<1, 256, 5><<<dim3(8, B_ROWS / 128), 256, G2_SMEM>>>(
                zh, w2h + woff, x0h, xh, bias + (size_t)i * D_DIM, nullptr, nullptr,
                out, nullptr, D_DIM);
        }
    }
}